// round 1
// baseline (speedup 1.0000x reference)
#include <cuda_runtime.h>
#include <math.h>

#define B_ 2
#define S_ 2048
#define D_ 1024
#define H_ 16
#define DH_ 64
#define NTOK (B_ * S_)              // 4096
#define OUT_ELEMS ((size_t)NTOK * D_)   // 4,194,304

// ---------------- scratch (device globals; no allocation allowed) ------------
__device__ float g_qh[(size_t)NTOK * D_];     // (B,H,S,DH) layout
__device__ float g_kh[(size_t)NTOK * D_];
__device__ float g_vh[(size_t)NTOK * D_];
__device__ float g_concat[(size_t)NTOK * D_]; // (B,S,D) layout

// ---------------- projection / output GEMM ----------------------------------
// Y = X(4096x1024) @ W(1024x1024) + bias
// mode 0/1/2: write head-split into g_qh/g_kh/g_vh.  mode 3: X := g_concat, write Y plain.
#define PBM 64
#define PBN 64
#define PBK 16

__global__ __launch_bounds__(256) void proj_gemm(const float* __restrict__ Xin,
                                                 const float* __restrict__ W,
                                                 const float* __restrict__ bias,
                                                 float* __restrict__ Yout,
                                                 int mode)
{
    __shared__ float As[PBK][PBM + 4];
    __shared__ float Bs[PBK][PBN + 4];

    const float* X = (mode == 3) ? g_concat : Xin;

    const int bm = blockIdx.y * PBM;
    const int bn = blockIdx.x * PBN;
    const int t  = threadIdx.x;          // 0..255
    const int tx = t & 15;               // 0..15
    const int ty = t >> 4;               // 0..15

    // load indices
    const int a_row = t >> 2;            // 0..63
    const int a_col = (t & 3) * 4;       // 0,4,8,12
    const int b_row = t >> 4;            // 0..15
    const int b_col = (t & 15) * 4;      // 0..60

    float acc[4][4];
#pragma unroll
    for (int i = 0; i < 4; i++)
#pragma unroll
        for (int j = 0; j < 4; j++) acc[i][j] = 0.0f;

    for (int k0 = 0; k0 < D_; k0 += PBK) {
        // A tile: 64 rows x 16 k
        {
            const float* Ap = X + (size_t)(bm + a_row) * D_ + k0 + a_col;
            float4 av = *(const float4*)Ap;
            As[a_col + 0][a_row] = av.x;
            As[a_col + 1][a_row] = av.y;
            As[a_col + 2][a_row] = av.z;
            As[a_col + 3][a_row] = av.w;
        }
        // B tile: 16 k x 64 cols
        {
            const float* Bp = W + (size_t)(k0 + b_row) * D_ + bn + b_col;
            float4 bv = *(const float4*)Bp;
            Bs[b_row][b_col + 0] = bv.x;
            Bs[b_row][b_col + 1] = bv.y;
            Bs[b_row][b_col + 2] = bv.z;
            Bs[b_row][b_col + 3] = bv.w;
        }
        __syncthreads();

#pragma unroll
        for (int k = 0; k < PBK; k++) {
            float a[4], b[4];
#pragma unroll
            for (int i = 0; i < 4; i++) a[i] = As[k][ty * 4 + i];
#pragma unroll
            for (int j = 0; j < 4; j++) b[j] = Bs[k][tx * 4 + j];
#pragma unroll
            for (int i = 0; i < 4; i++)
#pragma unroll
                for (int j = 0; j < 4; j++) acc[i][j] = fmaf(a[i], b[j], acc[i][j]);
        }
        __syncthreads();
    }

    float* dst;
    if (mode == 0) dst = g_qh;
    else if (mode == 1) dst = g_kh;
    else if (mode == 2) dst = g_vh;
    else dst = Yout;

#pragma unroll
    for (int i = 0; i < 4; i++) {
        const int row = bm + ty * 4 + i;          // token index
#pragma unroll
        for (int j = 0; j < 4; j++) {
            const int col = bn + tx * 4 + j;      // model-dim index
            const float y = acc[i][j] + bias[col];
            if (mode < 3) {
                // head-split: (b, h, s, d)
                const int bb = row >> 11;         // /2048
                const int ss = row & (S_ - 1);
                const int hh = col >> 6;
                const int dd = col & (DH_ - 1);
                dst[(((size_t)(bb * H_ + hh) * S_) + ss) * DH_ + dd] = y;
            } else {
                dst[(size_t)row * D_ + col] = y;
            }
        }
    }
}

// ---------------- logits: attn[bh, q, k] = scale * qh . kh ------------------
// Whole K-reduction (DH=64) fits in one tile pair.
__global__ __launch_bounds__(256) void logits_kernel(float* __restrict__ attn)
{
    __shared__ float Qs[64][DH_ + 1];
    __shared__ float Ks[64][DH_ + 1];

    const int bh = blockIdx.z;
    const int q0 = blockIdx.y * 64;
    const int k0 = blockIdx.x * 64;
    const float* Q = g_qh + (size_t)bh * S_ * DH_;
    const float* K = g_kh + (size_t)bh * S_ * DH_;
    float* Out = attn + (size_t)bh * S_ * S_;

    const int t  = threadIdx.x;
    const int tx = t & 15;
    const int ty = t >> 4;

    // load 64x64 tiles (16 elements / thread, coalesced)
#pragma unroll
    for (int i = 0; i < 16; i++) {
        const int e = i * 256 + t;               // 0..4095
        const int r = e >> 6, c = e & 63;
        Qs[r][c] = Q[(size_t)(q0 + r) * DH_ + c];
        Ks[r][c] = K[(size_t)(k0 + r) * DH_ + c];
    }
    __syncthreads();

    float acc[4][4];
#pragma unroll
    for (int i = 0; i < 4; i++)
#pragma unroll
        for (int j = 0; j < 4; j++) acc[i][j] = 0.0f;

#pragma unroll
    for (int d = 0; d < DH_; d++) {
        float a[4], b[4];
#pragma unroll
        for (int i = 0; i < 4; i++) a[i] = Qs[ty * 4 + i][d];
#pragma unroll
        for (int j = 0; j < 4; j++) b[j] = Ks[tx * 4 + j][d];
#pragma unroll
        for (int i = 0; i < 4; i++)
#pragma unroll
            for (int j = 0; j < 4; j++) acc[i][j] = fmaf(a[i], b[j], acc[i][j]);
    }

    const float scale = 0.125f;  // 1/sqrt(64)
#pragma unroll
    for (int i = 0; i < 4; i++) {
        const int qr = q0 + ty * 4 + i;
#pragma unroll
        for (int j = 0; j < 4; j++) {
            Out[(size_t)qr * S_ + k0 + tx * 4 + j] = acc[i][j] * scale;
        }
    }
}

// ---------------- softmax over last dim (2048), in place --------------------
__global__ __launch_bounds__(256) void softmax_kernel(float* __restrict__ attn)
{
    float* row = attn + (size_t)blockIdx.x * S_;
    const int t = threadIdx.x;
    const int lane = t & 31, wid = t >> 5;
    __shared__ float sm[8];
    __shared__ float bcast;

    float v[8];
    float m = -INFINITY;
#pragma unroll
    for (int i = 0; i < 8; i++) {
        v[i] = row[t + i * 256];
        m = fmaxf(m, v[i]);
    }
#pragma unroll
    for (int o = 16; o > 0; o >>= 1) m = fmaxf(m, __shfl_xor_sync(0xffffffffu, m, o));
    if (lane == 0) sm[wid] = m;
    __syncthreads();
    if (t == 0) {
        float mm = sm[0];
#pragma unroll
        for (int i = 1; i < 8; i++) mm = fmaxf(mm, sm[i]);
        bcast = mm;
    }
    __syncthreads();
    m = bcast;

    float s = 0.0f;
#pragma unroll
    for (int i = 0; i < 8; i++) {
        v[i] = __expf(v[i] - m);
        s += v[i];
    }
#pragma unroll
    for (int o = 16; o > 0; o >>= 1) s += __shfl_xor_sync(0xffffffffu, s, o);
    if (lane == 0) sm[wid] = s;
    __syncthreads();
    if (t == 0) {
        float ss = 0.0f;
#pragma unroll
        for (int i = 0; i < 8; i++) ss += sm[i];
        bcast = 1.0f / ss;
    }
    __syncthreads();
    const float inv = bcast;
#pragma unroll
    for (int i = 0; i < 8; i++) row[t + i * 256] = v[i] * inv;
}

// ---------------- attn @ V -> concat (B,S,D) --------------------------------
#define ABK 32
__global__ __launch_bounds__(256) void attnv_kernel(const float* __restrict__ attn)
{
    __shared__ float As[64][ABK + 1];   // [q_row][k]
    __shared__ float Vs[ABK][DH_ + 4];  // [k][d]

    const int bh = blockIdx.y;
    const int q0 = blockIdx.x * 64;
    const float* A = attn + (size_t)bh * S_ * S_;
    const float* V = g_vh + (size_t)bh * S_ * DH_;

    const int t  = threadIdx.x;
    const int tx = t & 15;
    const int ty = t >> 4;

    float acc[4][4];
#pragma unroll
    for (int i = 0; i < 4; i++)
#pragma unroll
        for (int j = 0; j < 4; j++) acc[i][j] = 0.0f;

    for (int k0 = 0; k0 < S_; k0 += ABK) {
        // attn tile 64 x 32 (8 elems/thread)
#pragma unroll
        for (int i = 0; i < 8; i++) {
            const int e = i * 256 + t;              // 0..2047
            const int r = e >> 5, c = e & 31;
            As[r][c] = A[(size_t)(q0 + r) * S_ + k0 + c];
        }
        // V tile 32 x 64
#pragma unroll
        for (int i = 0; i < 8; i++) {
            const int e = i * 256 + t;
            const int r = e >> 6, c = e & 63;
            Vs[r][c] = V[(size_t)(k0 + r) * DH_ + c];
        }
        __syncthreads();

#pragma unroll
        for (int k = 0; k < ABK; k++) {
            float a[4], b[4];
#pragma unroll
            for (int i = 0; i < 4; i++) a[i] = As[ty * 4 + i][k];
#pragma unroll
            for (int j = 0; j < 4; j++) b[j] = Vs[k][tx * 4 + j];
#pragma unroll
            for (int i = 0; i < 4; i++)
#pragma unroll
                for (int j = 0; j < 4; j++) acc[i][j] = fmaf(a[i], b[j], acc[i][j]);
        }
        __syncthreads();
    }

    const int bb = bh >> 4;     // /H
    const int hh = bh & (H_ - 1);
#pragma unroll
    for (int i = 0; i < 4; i++) {
        const int ss = q0 + ty * 4 + i;
#pragma unroll
        for (int j = 0; j < 4; j++) {
            const int dd = tx * 4 + j;
            g_concat[((size_t)(bb * S_ + ss)) * D_ + hh * DH_ + dd] = acc[i][j];
        }
    }
}

// ---------------- launch ----------------------------------------------------
extern "C" void kernel_launch(void* const* d_in, const int* in_sizes, int n_in,
                              void* d_out, int out_size)
{
    const float* q  = (const float*)d_in[0];
    const float* k  = (const float*)d_in[1];
    const float* v  = (const float*)d_in[2];
    const float* Wq = (const float*)d_in[3];
    const float* bq = (const float*)d_in[4];
    const float* Wk = (const float*)d_in[5];
    const float* bk = (const float*)d_in[6];
    const float* Wv = (const float*)d_in[7];
    const float* bv = (const float*)d_in[8];
    const float* Wc = (const float*)d_in[9];
    const float* bc = (const float*)d_in[10];

    float* out  = (float*)d_out;                 // (B,S,D)
    float* attn = out + OUT_ELEMS;               // (B,H,S,S)

    dim3 gproj(D_ / PBN, NTOK / PBM);            // 16 x 64
    proj_gemm<<<gproj, 256>>>(q, Wq, bq, nullptr, 0);
    proj_gemm<<<gproj, 256>>>(k, Wk, bk, nullptr, 1);
    proj_gemm<<<gproj, 256>>>(v, Wv, bv, nullptr, 2);

    dim3 glog(S_ / 64, S_ / 64, B_ * H_);        // 32 x 32 x 32
    logits_kernel<<<glog, 256>>>(attn);

    softmax_kernel<<<B_ * H_ * S_, 256>>>(attn); // 65536 rows

    dim3 gav(S_ / 64, B_ * H_);                  // 32 x 32
    attnv_kernel<<<gav, 256>>>(attn);

    proj_gemm<<<gproj, 256>>>(nullptr, Wc, bc, out, 3);
}

// round 3
// speedup vs baseline: 1.6028x; 1.6028x over previous
#include <cuda_runtime.h>
#include <cuda_bf16.h>
#include <math.h>
#include <stdint.h>

#define B_ 2
#define S_ 2048
#define D_ 1024
#define H_ 16
#define DH_ 64
#define NTOK (B_ * S_)
#define OUT_ELEMS ((size_t)NTOK * D_)

// ---------------- scratch ----------------------------------------------------
__device__ float g_qh[(size_t)NTOK * D_];     // (B,H,S,DH)
__device__ float g_kh[(size_t)NTOK * D_];
__device__ float g_vh[(size_t)NTOK * D_];
__device__ float g_concat[(size_t)NTOK * D_]; // (B,S,D)

// ---------------- helpers -----------------------------------------------------
__device__ __forceinline__ uint32_t smem_u32(const void* p) {
    uint32_t a;
    asm("{ .reg .u64 t; cvta.to.shared.u64 t, %1; cvt.u32.u64 %0, t; }" : "=r"(a) : "l"(p));
    return a;
}

__device__ __forceinline__ void mma_bf16(float c[4], const uint32_t a[4],
                                         uint32_t b0, uint32_t b1) {
    asm volatile("mma.sync.aligned.m16n8k16.row.col.f32.bf16.bf16.f32 "
        "{%0,%1,%2,%3}, {%4,%5,%6,%7}, {%8,%9}, {%0,%1,%2,%3};"
        : "+f"(c[0]), "+f"(c[1]), "+f"(c[2]), "+f"(c[3])
        : "r"(a[0]), "r"(a[1]), "r"(a[2]), "r"(a[3]), "r"(b0), "r"(b1));
}
__device__ __forceinline__ void ldsm4(uint32_t r[4], uint32_t a) {
    asm volatile("ldmatrix.sync.aligned.m8n8.x4.shared.b16 {%0,%1,%2,%3}, [%4];"
        : "=r"(r[0]), "=r"(r[1]), "=r"(r[2]), "=r"(r[3]) : "r"(a));
}
__device__ __forceinline__ void ldsm4t(uint32_t r[4], uint32_t a) {
    asm volatile("ldmatrix.sync.aligned.m8n8.x4.trans.shared.b16 {%0,%1,%2,%3}, [%4];"
        : "=r"(r[0]), "=r"(r[1]), "=r"(r[2]), "=r"(r[3]) : "r"(a));
}

// split fp32 pair -> bf16x2 hi, lo (low element = first k)
__device__ __forceinline__ void split2(float x, float y, uint32_t& hi, uint32_t& lo) {
    __nv_bfloat16 hx = __float2bfloat16(x), hy = __float2bfloat16(y);
    __nv_bfloat16 lx = __float2bfloat16(x - __bfloat162float(hx));
    __nv_bfloat16 ly = __float2bfloat16(y - __bfloat162float(hy));
    __nv_bfloat162 h(hx, hy), l(lx, ly);
    hi = *(uint32_t*)&h;
    lo = *(uint32_t*)&l;
}

// ---------------- projection GEMM: Y[4096,1024] = X @ W + b ------------------
// CTA 128x128, 8 warps (warp 64x32), K-chunk 64, double-buffered smem.
// buffer layout (64KB): AH 0, AL 16K, BH 32K, BL 48K.  buf stride 64K.
__global__ void __launch_bounds__(256, 1)
proj_tc(const float* __restrict__ Xin, const float* __restrict__ W,
        const float* __restrict__ bias, float* __restrict__ Yout, int mode)
{
    extern __shared__ __align__(1024) char smp[];
    uint32_t sb = smem_u32(smp);
    const int t = threadIdx.x, lane = t & 31, wid = t >> 5;
    const int wy = wid >> 2, wx = wid & 3;
    const float* X = (mode == 3) ? g_concat : Xin;
    const int bm = blockIdx.y * 128, bn = blockIdx.x * 128;

    float acc[4][4][4];
#pragma unroll
    for (int i = 0; i < 4; i++)
#pragma unroll
        for (int j = 0; j < 4; j++)
#pragma unroll
            for (int k = 0; k < 4; k++) acc[i][j][k] = 0.0f;

    float4 ra[8], rb[8];
    const int arow = t >> 4, ac4 = t & 15;      // A: r = i*16+arow, c4 fixed
    const int bk = t >> 5, bn4 = t & 31;        // B: k = i*8+bk, n4 fixed

#define P_LOADA(kc) do { _Pragma("unroll") \
    for (int i = 0; i < 8; i++) \
        ra[i] = *(const float4*)(X + (size_t)(bm + i * 16 + arow) * D_ + (kc) + ac4 * 4); \
} while (0)
#define P_LOADB(kc) do { _Pragma("unroll") \
    for (int i = 0; i < 8; i++) \
        rb[i] = *(const float4*)(W + (size_t)((kc) + i * 8 + bk) * D_ + bn + bn4 * 4); \
} while (0)
#define P_STORE(bo) do { _Pragma("unroll") \
    for (int i = 0; i < 8; i++) { \
        int r = i * 16 + arow; \
        uint32_t h01, l01, h23, l23; \
        split2(ra[i].x, ra[i].y, h01, l01); \
        split2(ra[i].z, ra[i].w, h23, l23); \
        uint32_t so = r * 128 + ((((ac4 >> 1) ^ (r & 7)) << 4)) + (ac4 & 1) * 8; \
        *(uint2*)(smp + (bo) + so)          = make_uint2(h01, h23); \
        *(uint2*)(smp + (bo) + 16384 + so)  = make_uint2(l01, l23); \
    } \
    _Pragma("unroll") \
    for (int i = 0; i < 8; i++) { \
        int k = i * 8 + bk; \
        uint32_t h01, l01, h23, l23; \
        split2(rb[i].x, rb[i].y, h01, l01); \
        split2(rb[i].z, rb[i].w, h23, l23); \
        uint32_t so = k * 256 + ((((bn4 >> 1) ^ (k & 7)) << 4)) + (bn4 & 1) * 8; \
        *(uint2*)(smp + (bo) + 32768 + so)  = make_uint2(h01, h23); \
        *(uint2*)(smp + (bo) + 49152 + so)  = make_uint2(l01, l23); \
    } \
} while (0)

#define P_MMA(bo) do { \
    uint32_t aAH = sb + (bo), aAL = aAH + 16384, aBH = aAH + 32768, aBL = aAH + 49152; \
    _Pragma("unroll") \
    for (int s = 0; s < 4; s++) { \
        const int rA0 = wy * 64 + ((lane >> 3) & 1) * 8 + (lane & 7); \
        const int cA = 2 * s + (lane >> 4); \
        uint32_t ah[4][4], al[4][4]; \
        _Pragma("unroll") \
        for (int mi = 0; mi < 4; mi++) { \
            int r = rA0 + mi * 16; \
            uint32_t off = r * 128 + ((cA ^ (r & 7)) << 4); \
            ldsm4(ah[mi], aAH + off); \
            ldsm4(al[mi], aAL + off); \
        } \
        const int rB = 16 * s + ((lane >> 3) & 1) * 8 + (lane & 7); \
        uint32_t bh[2][4], bl[2][4]; \
        _Pragma("unroll") \
        for (int nh = 0; nh < 2; nh++) { \
            int cB = ((wx * 32 + nh * 16) >> 3) + ((lane >> 4) & 1); \
            uint32_t off = rB * 256 + ((cB ^ (rB & 7)) << 4); \
            ldsm4t(bh[nh], aBH + off); \
            ldsm4t(bl[nh], aBL + off); \
        } \
        _Pragma("unroll") \
        for (int mi = 0; mi < 4; mi++) \
            _Pragma("unroll") \
            for (int nj = 0; nj < 4; nj++) { \
                uint32_t bh0 = bh[nj >> 1][(nj & 1) * 2], bh1 = bh[nj >> 1][(nj & 1) * 2 + 1]; \
                uint32_t bl0 = bl[nj >> 1][(nj & 1) * 2], bl1 = bl[nj >> 1][(nj & 1) * 2 + 1]; \
                mma_bf16(acc[mi][nj], ah[mi], bh0, bh1); \
                mma_bf16(acc[mi][nj], ah[mi], bl0, bl1); \
                mma_bf16(acc[mi][nj], al[mi], bh0, bh1); \
            } \
    } \
} while (0)

    P_LOADA(0); P_LOADB(0); P_STORE(0);
    __syncthreads();
#pragma unroll 1
    for (int c = 0; c < 16; c++) {
        int cur = (c & 1) * 65536;
        if (c < 15) { P_LOADA((c + 1) * 64); P_LOADB((c + 1) * 64); }
        P_MMA(cur);
        if (c < 15) { P_STORE(65536 - cur); __syncthreads(); }
    }

    float* dst = (mode == 0) ? g_qh : (mode == 1) ? g_kh : (mode == 2) ? g_vh : Yout;
    const int er = lane >> 2, ec = (lane & 3) * 2;
#pragma unroll
    for (int mi = 0; mi < 4; mi++)
#pragma unroll
        for (int nj = 0; nj < 4; nj++) {
            const int col = bn + wx * 32 + nj * 8 + ec;
            const float b0 = __ldg(bias + col), b1 = __ldg(bias + col + 1);
            const int row0 = bm + wy * 64 + mi * 16 + er;
#pragma unroll
            for (int h = 0; h < 2; h++) {
                const int row = row0 + h * 8;
                float2 v = make_float2(acc[mi][nj][h * 2] + b0, acc[mi][nj][h * 2 + 1] + b1);
                if (mode < 3) {
                    int bb = row >> 11, ss = row & (S_ - 1), hh = col >> 6, dd = col & (DH_ - 1);
                    *(float2*)(dst + (((size_t)(bb * H_ + hh)) * S_ + ss) * DH_ + dd) = v;
                } else {
                    *(float2*)(dst + (size_t)row * D_ + col) = v;
                }
            }
        }
}

// ---------------- logits: attn = 0.125 * Q K^T -------------------------------
// CTA 128x128, k = DH = 64 (single chunk). smem: QH 0, QL 16K, KH 32K, KL 48K.
__global__ void __launch_bounds__(256, 1) logits_tc(float* __restrict__ attn)
{
    extern __shared__ __align__(1024) char smp[];
    uint32_t sb = smem_u32(smp);
    const int t = threadIdx.x, lane = t & 31, wid = t >> 5;
    const int wy = wid >> 2, wx = wid & 3;
    const int bh = blockIdx.z, q0 = blockIdx.y * 128, k0 = blockIdx.x * 128;
    const float* Q = g_qh + (size_t)bh * S_ * DH_;
    const float* K = g_kh + (size_t)bh * S_ * DH_;
    float* Out = attn + (size_t)bh * S_ * S_;

    const int arow = t >> 4, ac4 = t & 15;
#pragma unroll
    for (int i = 0; i < 8; i++) {
        const int r = i * 16 + arow;
        const uint32_t so = r * 128 + ((((ac4 >> 1) ^ (r & 7)) << 4)) + (ac4 & 1) * 8;
        float4 vq = *(const float4*)(Q + (size_t)(q0 + r) * DH_ + ac4 * 4);
        float4 vk = *(const float4*)(K + (size_t)(k0 + r) * DH_ + ac4 * 4);
        uint32_t h01, l01, h23, l23;
        split2(vq.x, vq.y, h01, l01); split2(vq.z, vq.w, h23, l23);
        *(uint2*)(smp + so)         = make_uint2(h01, h23);
        *(uint2*)(smp + 16384 + so) = make_uint2(l01, l23);
        split2(vk.x, vk.y, h01, l01); split2(vk.z, vk.w, h23, l23);
        *(uint2*)(smp + 32768 + so) = make_uint2(h01, h23);
        *(uint2*)(smp + 49152 + so) = make_uint2(l01, l23);
    }
    __syncthreads();

    float acc[4][4][4];
#pragma unroll
    for (int i = 0; i < 4; i++)
#pragma unroll
        for (int j = 0; j < 4; j++)
#pragma unroll
            for (int k = 0; k < 4; k++) acc[i][j][k] = 0.0f;

    const uint32_t aQH = sb, aQL = sb + 16384, aKH = sb + 32768, aKL = sb + 49152;
#pragma unroll
    for (int s = 0; s < 4; s++) {
        const int rA0 = wy * 64 + ((lane >> 3) & 1) * 8 + (lane & 7);
        const int cA = 2 * s + (lane >> 4);
        uint32_t ah[4][4], al[4][4];
#pragma unroll
        for (int mi = 0; mi < 4; mi++) {
            int r = rA0 + mi * 16;
            uint32_t off = r * 128 + ((cA ^ (r & 7)) << 4);
            ldsm4(ah[mi], aQH + off);
            ldsm4(al[mi], aQL + off);
        }
        // B non-trans: n-major [n][k]
        uint32_t bhf[2][4], blf[2][4];
        const int cB = 2 * s + ((lane >> 3) & 1);
#pragma unroll
        for (int nh = 0; nh < 2; nh++) {
            int r = wx * 32 + nh * 16 + ((lane >> 4) & 1) * 8 + (lane & 7);
            uint32_t off = r * 128 + ((cB ^ (r & 7)) << 4);
            ldsm4(bhf[nh], aKH + off);
            ldsm4(blf[nh], aKL + off);
        }
#pragma unroll
        for (int mi = 0; mi < 4; mi++)
#pragma unroll
            for (int nj = 0; nj < 4; nj++) {
                uint32_t b0 = bhf[nj >> 1][(nj & 1) * 2], b1 = bhf[nj >> 1][(nj & 1) * 2 + 1];
                uint32_t c0 = blf[nj >> 1][(nj & 1) * 2], c1 = blf[nj >> 1][(nj & 1) * 2 + 1];
                mma_bf16(acc[mi][nj], ah[mi], b0, b1);
                mma_bf16(acc[mi][nj], ah[mi], c0, c1);
                mma_bf16(acc[mi][nj], al[mi], b0, b1);
            }
    }

    const int er = lane >> 2, ec = (lane & 3) * 2;
#pragma unroll
    for (int mi = 0; mi < 4; mi++)
#pragma unroll
        for (int nj = 0; nj < 4; nj++) {
            const int col = k0 + wx * 32 + nj * 8 + ec;
            const int row0 = q0 + wy * 64 + mi * 16 + er;
#pragma unroll
            for (int h = 0; h < 2; h++) {
                float2 v = make_float2(acc[mi][nj][h * 2] * 0.125f,
                                       acc[mi][nj][h * 2 + 1] * 0.125f);
                *(float2*)(Out + (size_t)(row0 + h * 8) * S_ + col) = v;
            }
        }
}

// ---------------- softmax ----------------------------------------------------
__global__ void __launch_bounds__(256) softmax_kernel(float* __restrict__ attn)
{
    float* row = attn + (size_t)blockIdx.x * S_;
    const int t = threadIdx.x;
    const int lane = t & 31, wid = t >> 5;
    __shared__ float sm[8];
    __shared__ float bcast;

    float v[8];
    float m = -INFINITY;
#pragma unroll
    for (int i = 0; i < 8; i++) { v[i] = row[t + i * 256]; m = fmaxf(m, v[i]); }
#pragma unroll
    for (int o = 16; o > 0; o >>= 1) m = fmaxf(m, __shfl_xor_sync(0xffffffffu, m, o));
    if (lane == 0) sm[wid] = m;
    __syncthreads();
    if (t == 0) {
        float mm = sm[0];
#pragma unroll
        for (int i = 1; i < 8; i++) mm = fmaxf(mm, sm[i]);
        bcast = mm;
    }
    __syncthreads();
    m = bcast;

    float s = 0.0f;
#pragma unroll
    for (int i = 0; i < 8; i++) { v[i] = __expf(v[i] - m); s += v[i]; }
#pragma unroll
    for (int o = 16; o > 0; o >>= 1) s += __shfl_xor_sync(0xffffffffu, s, o);
    if (lane == 0) sm[wid] = s;
    __syncthreads();
    if (t == 0) {
        float ss = 0.0f;
#pragma unroll
        for (int i = 0; i < 8; i++) ss += sm[i];
        bcast = 1.0f / ss;
    }
    __syncthreads();
    const float inv = bcast;
#pragma unroll
    for (int i = 0; i < 8; i++) row[t + i * 256] = v[i] * inv;
}

// ---------------- attn @ V -> concat -----------------------------------------
// CTA 128q x 64d, 8 warps (warp 32x32). K-chunk 64, double-buffered.
// buffer layout (48KB): AH 0, AL 16K, BH 32K, BL 40K.  buf stride 48K.
__global__ void __launch_bounds__(256, 1) attnv_tc(const float* __restrict__ attn)
{
    extern __shared__ __align__(1024) char smp[];
    uint32_t sb = smem_u32(smp);
    const int t = threadIdx.x, lane = t & 31, wid = t >> 5;
    const int wy = wid >> 1, wx = wid & 1;
    const int bh = blockIdx.y, q0 = blockIdx.x * 128;
    const float* A = attn + (size_t)bh * S_ * S_;
    const float* V = g_vh + (size_t)bh * S_ * DH_;

    float acc[2][4][4];
#pragma unroll
    for (int i = 0; i < 2; i++)
#pragma unroll
        for (int j = 0; j < 4; j++)
#pragma unroll
            for (int k = 0; k < 4; k++) acc[i][j][k] = 0.0f;

    float4 ra[8], rv[4];
    const int arow = t >> 4, ac4 = t & 15;

#define V_LOADA(kc) do { _Pragma("unroll") \
    for (int i = 0; i < 8; i++) \
        ra[i] = *(const float4*)(A + (size_t)(q0 + i * 16 + arow) * S_ + (kc) + ac4 * 4); \
} while (0)
#define V_LOADV(kc) do { _Pragma("unroll") \
    for (int i = 0; i < 4; i++) \
        rv[i] = *(const float4*)(V + (size_t)((kc) + i * 16 + arow) * DH_ + ac4 * 4); \
} while (0)
#define V_STORE(bo) do { _Pragma("unroll") \
    for (int i = 0; i < 8; i++) { \
        int r = i * 16 + arow; \
        uint32_t h01, l01, h23, l23; \
        split2(ra[i].x, ra[i].y, h01, l01); \
        split2(ra[i].z, ra[i].w, h23, l23); \
        uint32_t so = r * 128 + ((((ac4 >> 1) ^ (r & 7)) << 4)) + (ac4 & 1) * 8; \
        *(uint2*)(smp + (bo) + so)         = make_uint2(h01, h23); \
        *(uint2*)(smp + (bo) + 16384 + so) = make_uint2(l01, l23); \
    } \
    _Pragma("unroll") \
    for (int i = 0; i < 4; i++) { \
        int k = i * 16 + arow; \
        uint32_t h01, l01, h23, l23; \
        split2(rv[i].x, rv[i].y, h01, l01); \
        split2(rv[i].z, rv[i].w, h23, l23); \
        uint32_t so = k * 128 + ((((ac4 >> 1) ^ (k & 7)) << 4)) + (ac4 & 1) * 8; \
        *(uint2*)(smp + (bo) + 32768 + so) = make_uint2(h01, h23); \
        *(uint2*)(smp + (bo) + 40960 + so) = make_uint2(l01, l23); \
    } \
} while (0)
#define V_MMA(bo) do { \
    uint32_t aAH = sb + (bo), aAL = aAH + 16384, aBH = aAH + 32768, aBL = aAH + 40960; \
    _Pragma("unroll") \
    for (int s = 0; s < 4; s++) { \
        const int rA0 = wy * 32 + ((lane >> 3) & 1) * 8 + (lane & 7); \
        const int cA = 2 * s + (lane >> 4); \
        uint32_t ah[2][4], al[2][4]; \
        _Pragma("unroll") \
        for (int mi = 0; mi < 2; mi++) { \
            int r = rA0 + mi * 16; \
            uint32_t off = r * 128 + ((cA ^ (r & 7)) << 4); \
            ldsm4(ah[mi], aAH + off); \
            ldsm4(al[mi], aAL + off); \
        } \
        const int rB = 16 * s + ((lane >> 3) & 1) * 8 + (lane & 7); \
        uint32_t bh2[2][4], bl2[2][4]; \
        _Pragma("unroll") \
        for (int nh = 0; nh < 2; nh++) { \
            int cB = ((wx * 32 + nh * 16) >> 3) + ((lane >> 4) & 1); \
            uint32_t off = rB * 128 + ((cB ^ (rB & 7)) << 4); \
            ldsm4t(bh2[nh], aBH + off); \
            ldsm4t(bl2[nh], aBL + off); \
        } \
        _Pragma("unroll") \
        for (int mi = 0; mi < 2; mi++) \
            _Pragma("unroll") \
            for (int nj = 0; nj < 4; nj++) { \
                uint32_t b0 = bh2[nj >> 1][(nj & 1) * 2], b1 = bh2[nj >> 1][(nj & 1) * 2 + 1]; \
                uint32_t c0 = bl2[nj >> 1][(nj & 1) * 2], c1 = bl2[nj >> 1][(nj & 1) * 2 + 1]; \
                mma_bf16(acc[mi][nj], ah[mi], b0, b1); \
                mma_bf16(acc[mi][nj], ah[mi], c0, c1); \
                mma_bf16(acc[mi][nj], al[mi], b0, b1); \
            } \
    } \
} while (0)

    V_LOADA(0); V_LOADV(0); V_STORE(0);
    __syncthreads();
#pragma unroll 1
    for (int c = 0; c < 32; c++) {
        int cur = (c & 1) * 49152;
        if (c < 31) { V_LOADA((c + 1) * 64); V_LOADV((c + 1) * 64); }
        V_MMA(cur);
        if (c < 31) { V_STORE(49152 - cur); __syncthreads(); }
    }

    const int bb = bh >> 4, hh = bh & (H_ - 1);
    const int er = lane >> 2, ec = (lane & 3) * 2;
#pragma unroll
    for (int mi = 0; mi < 2; mi++)
#pragma unroll
        for (int nj = 0; nj < 4; nj++) {
            const int dd = wx * 32 + nj * 8 + ec;
            const int row0 = q0 + wy * 32 + mi * 16 + er;
#pragma unroll
            for (int h = 0; h < 2; h++) {
                const int ss = row0 + h * 8;
                float2 v = make_float2(acc[mi][nj][h * 2], acc[mi][nj][h * 2 + 1]);
                *(float2*)(g_concat + ((size_t)(bb * S_ + ss)) * D_ + hh * DH_ + dd) = v;
            }
        }
}

// ---------------- launch ------------------------------------------------------
extern "C" void kernel_launch(void* const* d_in, const int* in_sizes, int n_in,
                              void* d_out, int out_size)
{
    const float* q  = (const float*)d_in[0];
    const float* k  = (const float*)d_in[1];
    const float* v  = (const float*)d_in[2];
    const float* Wq = (const float*)d_in[3];
    const float* bq = (const float*)d_in[4];
    const float* Wk = (const float*)d_in[5];
    const float* bk = (const float*)d_in[6];
    const float* Wv = (const float*)d_in[7];
    const float* bv = (const float*)d_in[8];
    const float* Wc = (const float*)d_in[9];
    const float* bc = (const float*)d_in[10];

    float* out  = (float*)d_out;
    float* attn = out + OUT_ELEMS;

    const int SM_PROJ = 131072;
    const int SM_LOG  = 65536;
    const int SM_AV   = 98304;
    cudaFuncSetAttribute(proj_tc,   cudaFuncAttributeMaxDynamicSharedMemorySize, SM_PROJ);
    cudaFuncSetAttribute(logits_tc, cudaFuncAttributeMaxDynamicSharedMemorySize, SM_LOG);
    cudaFuncSetAttribute(attnv_tc,  cudaFuncAttributeMaxDynamicSharedMemorySize, SM_AV);

    dim3 gp(D_ / 128, NTOK / 128);          // 8 x 32
    proj_tc<<<gp, 256, SM_PROJ>>>(q, Wq, bq, nullptr, 0);
    proj_tc<<<gp, 256, SM_PROJ>>>(k, Wk, bk, nullptr, 1);
    proj_tc<<<gp, 256, SM_PROJ>>>(v, Wv, bv, nullptr, 2);

    dim3 gl(S_ / 128, S_ / 128, B_ * H_);   // 16 x 16 x 32
    logits_tc<<<gl, 256, SM_LOG>>>(attn);

    softmax_kernel<<<B_ * H_ * S_, 256>>>(attn);

    dim3 ga(S_ / 128, B_ * H_);             // 16 x 32
    attnv_tc<<<ga, 256, SM_AV>>>(attn);

    proj_tc<<<gp, 256, SM_PROJ>>>(nullptr, Wc, bc, out, 3);
}

// round 4
// speedup vs baseline: 2.5458x; 1.5884x over previous
#include <cuda_runtime.h>
#include <cuda_bf16.h>
#include <math.h>
#include <stdint.h>

#define B_ 2
#define S_ 2048
#define D_ 1024
#define H_ 16
#define DH_ 64
#define NTOK 4096
#define OUT_ELEMS ((size_t)NTOK * D_)
#define NROW 65536   // B*H*S

// ---------------- pre-split bf16 hi/lo scratch -------------------------------
__device__ __nv_bfloat16 g_xs_h[3][(size_t)NTOK * D_];
__device__ __nv_bfloat16 g_xs_l[3][(size_t)NTOK * D_];
__device__ __nv_bfloat16 g_ws_h[4][(size_t)D_ * D_];
__device__ __nv_bfloat16 g_ws_l[4][(size_t)D_ * D_];
__device__ __nv_bfloat16 g_hd_h[3][(size_t)NTOK * D_];   // head-split q/k/v
__device__ __nv_bfloat16 g_hd_l[3][(size_t)NTOK * D_];
__device__ __nv_bfloat16 g_cat_h[(size_t)NTOK * D_];
__device__ __nv_bfloat16 g_cat_l[(size_t)NTOK * D_];
__device__ float g_st_max[(size_t)NROW * 16];
__device__ float g_st_sum[(size_t)NROW * 16];
__device__ float g_row_m[NROW];
__device__ float g_row_inv[NROW];

// ---------------- helpers -----------------------------------------------------
__device__ __forceinline__ uint32_t smem_u32(const void* p) {
    uint32_t a;
    asm("{ .reg .u64 t; cvta.to.shared.u64 t, %1; cvt.u32.u64 %0, t; }" : "=r"(a) : "l"(p));
    return a;
}
__device__ __forceinline__ void mma_bf16(float c[4], const uint32_t a[4],
                                         uint32_t b0, uint32_t b1) {
    asm volatile("mma.sync.aligned.m16n8k16.row.col.f32.bf16.bf16.f32 "
        "{%0,%1,%2,%3}, {%4,%5,%6,%7}, {%8,%9}, {%0,%1,%2,%3};"
        : "+f"(c[0]), "+f"(c[1]), "+f"(c[2]), "+f"(c[3])
        : "r"(a[0]), "r"(a[1]), "r"(a[2]), "r"(a[3]), "r"(b0), "r"(b1));
}
__device__ __forceinline__ void ldsm4(uint32_t r[4], uint32_t a) {
    asm volatile("ldmatrix.sync.aligned.m8n8.x4.shared.b16 {%0,%1,%2,%3}, [%4];"
        : "=r"(r[0]), "=r"(r[1]), "=r"(r[2]), "=r"(r[3]) : "r"(a));
}
__device__ __forceinline__ void ldsm4t(uint32_t r[4], uint32_t a) {
    asm volatile("ldmatrix.sync.aligned.m8n8.x4.trans.shared.b16 {%0,%1,%2,%3}, [%4];"
        : "=r"(r[0]), "=r"(r[1]), "=r"(r[2]), "=r"(r[3]) : "r"(a));
}
__device__ __forceinline__ void split2(float x, float y, uint32_t& hi, uint32_t& lo) {
    __nv_bfloat16 hx = __float2bfloat16(x), hy = __float2bfloat16(y);
    __nv_bfloat16 lx = __float2bfloat16(x - __bfloat162float(hx));
    __nv_bfloat16 ly = __float2bfloat16(y - __bfloat162float(hy));
    __nv_bfloat162 h(hx, hy), l(lx, ly);
    hi = *(uint32_t*)&h;
    lo = *(uint32_t*)&l;
}
__device__ __forceinline__ void cp16(uint32_t smem, const void* g) {
    asm volatile("cp.async.cg.shared.global [%0], [%1], 16;" :: "r"(smem), "l"(g));
}
#define CP_COMMIT() asm volatile("cp.async.commit_group;" ::: "memory")
template<int N> __device__ __forceinline__ void cp_wait() {
    asm volatile("cp.async.wait_group %0;" :: "n"(N) : "memory");
}

// ---------------- prep: split inputs + weights --------------------------------
__global__ void __launch_bounds__(256) split_all(
    const float* __restrict__ q, const float* __restrict__ k, const float* __restrict__ v,
    const float* __restrict__ wq, const float* __restrict__ wk,
    const float* __restrict__ wv, const float* __restrict__ wc)
{
    int i = blockIdx.x * 256 + threadIdx.x;          // float4 index
    const float* src;
    __nv_bfloat16 *dh, *dl;
    int off;
    if (i < 3 * 1048576) {
        int ti = i >> 20; off = i & 1048575;
        src = (ti == 0) ? q : (ti == 1) ? k : v;
        dh = g_xs_h[ti]; dl = g_xs_l[ti];
    } else {
        int j = i - 3145728;
        int ti = j >> 18; off = j & 262143;
        src = (ti == 0) ? wq : (ti == 1) ? wk : (ti == 2) ? wv : wc;
        dh = g_ws_h[ti]; dl = g_ws_l[ti];
    }
    float4 x = ((const float4*)src)[off];
    uint32_t h01, l01, h23, l23;
    split2(x.x, x.y, h01, l01);
    split2(x.z, x.w, h23, l23);
    ((uint2*)dh)[off] = make_uint2(h01, h23);
    ((uint2*)dl)[off] = make_uint2(l01, l23);
}

// ---------------- projection GEMM (cp.async, 3-stage) -------------------------
// CTA 128x128, 8 warps (64x32), K-chunk 64. buffer 64KB: AH 0, AL 16K, BH 32K, BL 48K.
__global__ void __launch_bounds__(256, 1)
proj_tc(const float* __restrict__ bq, const float* __restrict__ bk,
        const float* __restrict__ bv, const float* __restrict__ bc,
        float* __restrict__ Yout, int mode_base)
{
    extern __shared__ __align__(1024) char smp[];
    uint32_t sb = smem_u32(smp);
    const int t = threadIdx.x, lane = t & 31, wid = t >> 5;
    const int wy = wid >> 2, wx = wid & 3;
    const int mode = mode_base + blockIdx.z;
    const __nv_bfloat16 *Xh, *Xl;
    if (mode < 3) { Xh = g_xs_h[mode]; Xl = g_xs_l[mode]; }
    else          { Xh = g_cat_h;      Xl = g_cat_l; }
    const __nv_bfloat16 *Wh = g_ws_h[mode], *Wl = g_ws_l[mode];
    const float* bias = (mode == 0) ? bq : (mode == 1) ? bk : (mode == 2) ? bv : bc;
    const int bm = blockIdx.y * 128, bn = blockIdx.x * 128;

    float acc[4][4][4];
#pragma unroll
    for (int i = 0; i < 4; i++)
#pragma unroll
        for (int j = 0; j < 4; j++)
#pragma unroll
            for (int k = 0; k < 4; k++) acc[i][j][k] = 0.0f;

#define PJ_PF(c) do { \
    const int kc_ = (c) * 64; \
    uint32_t bo_ = sb + ((c) % 3) * 65536; \
    _Pragma("unroll") \
    for (int i_ = 0; i_ < 4; i_++) { \
        int e_ = i_ * 256 + t, r_ = e_ >> 3, c8_ = e_ & 7; \
        uint32_t so_ = r_ * 128 + ((c8_ ^ (r_ & 7)) << 4); \
        const size_t g_ = (size_t)(bm + r_) * D_ + kc_ + c8_ * 8; \
        cp16(bo_ + so_,         Xh + g_); \
        cp16(bo_ + 16384 + so_, Xl + g_); \
    } \
    _Pragma("unroll") \
    for (int i_ = 0; i_ < 4; i_++) { \
        int e_ = i_ * 256 + t, k_ = e_ >> 4, b_ = e_ & 15; \
        uint32_t so_ = k_ * 256 + ((b_ ^ (k_ & 7)) << 4); \
        const size_t g_ = (size_t)(kc_ + k_) * D_ + bn + b_ * 8; \
        cp16(bo_ + 32768 + so_, Wh + g_); \
        cp16(bo_ + 49152 + so_, Wl + g_); \
    } \
    CP_COMMIT(); \
} while (0)

#define PJ_MMA(base) do { \
    uint32_t aAH = (base), aAL = (base) + 16384, aBH = (base) + 32768, aBL = (base) + 49152; \
    _Pragma("unroll") \
    for (int s = 0; s < 4; s++) { \
        const int rA0 = wy * 64 + ((lane >> 3) & 1) * 8 + (lane & 7); \
        const int cA = 2 * s + (lane >> 4); \
        uint32_t ah[4][4], al[4][4]; \
        _Pragma("unroll") \
        for (int mi = 0; mi < 4; mi++) { \
            int r = rA0 + mi * 16; \
            uint32_t off = r * 128 + ((cA ^ (r & 7)) << 4); \
            ldsm4(ah[mi], aAH + off); \
            ldsm4(al[mi], aAL + off); \
        } \
        const int rB = 16 * s + ((lane >> 3) & 1) * 8 + (lane & 7); \
        uint32_t bh[2][4], bl[2][4]; \
        _Pragma("unroll") \
        for (int nh = 0; nh < 2; nh++) { \
            int cB = ((wx * 32 + nh * 16) >> 3) + ((lane >> 4) & 1); \
            uint32_t off = rB * 256 + ((cB ^ (rB & 7)) << 4); \
            ldsm4t(bh[nh], aBH + off); \
            ldsm4t(bl[nh], aBL + off); \
        } \
        _Pragma("unroll") \
        for (int mi = 0; mi < 4; mi++) \
            _Pragma("unroll") \
            for (int nj = 0; nj < 4; nj++) { \
                uint32_t bh0 = bh[nj >> 1][(nj & 1) * 2], bh1 = bh[nj >> 1][(nj & 1) * 2 + 1]; \
                uint32_t bl0 = bl[nj >> 1][(nj & 1) * 2], bl1 = bl[nj >> 1][(nj & 1) * 2 + 1]; \
                mma_bf16(acc[mi][nj], ah[mi], bh0, bh1); \
                mma_bf16(acc[mi][nj], ah[mi], bl0, bl1); \
                mma_bf16(acc[mi][nj], al[mi], bh0, bh1); \
            } \
    } \
} while (0)

    PJ_PF(0); PJ_PF(1);
#pragma unroll 1
    for (int c = 0; c < 16; c++) {
        if (c + 2 < 16) PJ_PF(c + 2);
        if (c < 14) cp_wait<2>(); else if (c == 14) cp_wait<1>(); else cp_wait<0>();
        __syncthreads();
        PJ_MMA(sb + (c % 3) * 65536);
        __syncthreads();
    }

    const int er = lane >> 2, ec = (lane & 3) * 2;
    if (mode < 3) {
        __nv_bfloat16* dh = g_hd_h[mode];
        __nv_bfloat16* dl = g_hd_l[mode];
#pragma unroll
        for (int mi = 0; mi < 4; mi++)
#pragma unroll
            for (int nj = 0; nj < 4; nj++) {
                const int col = bn + wx * 32 + nj * 8 + ec;
                const float b0 = __ldg(bias + col), b1 = __ldg(bias + col + 1);
                const int row0 = bm + wy * 64 + mi * 16 + er;
#pragma unroll
                for (int h = 0; h < 2; h++) {
                    const int row = row0 + h * 8;
                    uint32_t hv, lv;
                    split2(acc[mi][nj][h * 2] + b0, acc[mi][nj][h * 2 + 1] + b1, hv, lv);
                    int bb = row >> 11, ss = row & (S_ - 1), hh = col >> 6, dd = col & (DH_ - 1);
                    size_t idx = (((size_t)(bb * H_ + hh)) * S_ + ss) * DH_ + dd;
                    *(uint32_t*)(dh + idx) = hv;
                    *(uint32_t*)(dl + idx) = lv;
                }
            }
    } else {
#pragma unroll
        for (int mi = 0; mi < 4; mi++)
#pragma unroll
            for (int nj = 0; nj < 4; nj++) {
                const int col = bn + wx * 32 + nj * 8 + ec;
                const float b0 = __ldg(bias + col), b1 = __ldg(bias + col + 1);
                const int row0 = bm + wy * 64 + mi * 16 + er;
#pragma unroll
                for (int h = 0; h < 2; h++) {
                    float2 v = make_float2(acc[mi][nj][h * 2] + b0, acc[mi][nj][h * 2 + 1] + b1);
                    *(float2*)(Yout + (size_t)(row0 + h * 8) * D_ + col) = v;
                }
            }
    }
}

// ---------------- logits: raw scaled logits + softmax tile stats --------------
__global__ void __launch_bounds__(256, 1) logits_tc(float* __restrict__ attn)
{
    extern __shared__ __align__(1024) char smp[];
    __shared__ float s_red[128][4];
    __shared__ float s_row[128];
    uint32_t sb = smem_u32(smp);
    const int t = threadIdx.x, lane = t & 31, wid = t >> 5;
    const int wy = wid >> 2, wx = wid & 3;
    const int bh = blockIdx.z, q0 = blockIdx.y * 128, k0 = blockIdx.x * 128;
    const int kt = blockIdx.x;
    const __nv_bfloat16* Qh = g_hd_h[0] + (size_t)bh * S_ * DH_;
    const __nv_bfloat16* Ql = g_hd_l[0] + (size_t)bh * S_ * DH_;
    const __nv_bfloat16* Kh = g_hd_h[1] + (size_t)bh * S_ * DH_;
    const __nv_bfloat16* Kl = g_hd_l[1] + (size_t)bh * S_ * DH_;
    float* Out = attn + (size_t)bh * S_ * S_;

#pragma unroll
    for (int i = 0; i < 4; i++) {
        int e = i * 256 + t, r = e >> 3, c8 = e & 7;
        uint32_t so = r * 128 + ((c8 ^ (r & 7)) << 4);
        cp16(sb + so,         Qh + (size_t)(q0 + r) * DH_ + c8 * 8);
        cp16(sb + 16384 + so, Ql + (size_t)(q0 + r) * DH_ + c8 * 8);
        cp16(sb + 32768 + so, Kh + (size_t)(k0 + r) * DH_ + c8 * 8);
        cp16(sb + 49152 + so, Kl + (size_t)(k0 + r) * DH_ + c8 * 8);
    }
    CP_COMMIT();
    cp_wait<0>();
    __syncthreads();

    float acc[4][4][4];
#pragma unroll
    for (int i = 0; i < 4; i++)
#pragma unroll
        for (int j = 0; j < 4; j++)
#pragma unroll
            for (int k = 0; k < 4; k++) acc[i][j][k] = 0.0f;

    const uint32_t aQH = sb, aQL = sb + 16384, aKH = sb + 32768, aKL = sb + 49152;
#pragma unroll
    for (int s = 0; s < 4; s++) {
        const int rA0 = wy * 64 + ((lane >> 3) & 1) * 8 + (lane & 7);
        const int cA = 2 * s + (lane >> 4);
        uint32_t ah[4][4], al[4][4];
#pragma unroll
        for (int mi = 0; mi < 4; mi++) {
            int r = rA0 + mi * 16;
            uint32_t off = r * 128 + ((cA ^ (r & 7)) << 4);
            ldsm4(ah[mi], aQH + off);
            ldsm4(al[mi], aQL + off);
        }
        uint32_t bhf[2][4], blf[2][4];
        const int cB = 2 * s + ((lane >> 3) & 1);
#pragma unroll
        for (int nh = 0; nh < 2; nh++) {
            int r = wx * 32 + nh * 16 + ((lane >> 4) & 1) * 8 + (lane & 7);
            uint32_t off = r * 128 + ((cB ^ (r & 7)) << 4);
            ldsm4(bhf[nh], aKH + off);
            ldsm4(blf[nh], aKL + off);
        }
#pragma unroll
        for (int mi = 0; mi < 4; mi++)
#pragma unroll
            for (int nj = 0; nj < 4; nj++) {
                uint32_t b0 = bhf[nj >> 1][(nj & 1) * 2], b1 = bhf[nj >> 1][(nj & 1) * 2 + 1];
                uint32_t c0 = blf[nj >> 1][(nj & 1) * 2], c1 = blf[nj >> 1][(nj & 1) * 2 + 1];
                mma_bf16(acc[mi][nj], ah[mi], b0, b1);
                mma_bf16(acc[mi][nj], ah[mi], c0, c1);
                mma_bf16(acc[mi][nj], al[mi], b0, b1);
            }
    }

#pragma unroll
    for (int i = 0; i < 4; i++)
#pragma unroll
        for (int j = 0; j < 4; j++)
#pragma unroll
            for (int k = 0; k < 4; k++) acc[i][j][k] *= 0.125f;

    const int er = lane >> 2, ec = (lane & 3) * 2;

    // per-tile row max
#pragma unroll
    for (int mi = 0; mi < 4; mi++)
#pragma unroll
        for (int h = 0; h < 2; h++) {
            float m = -1e30f;
#pragma unroll
            for (int nj = 0; nj < 4; nj++)
                m = fmaxf(m, fmaxf(acc[mi][nj][h * 2], acc[mi][nj][h * 2 + 1]));
            m = fmaxf(m, __shfl_xor_sync(0xffffffffu, m, 1));
            m = fmaxf(m, __shfl_xor_sync(0xffffffffu, m, 2));
            if ((lane & 3) == 0) s_red[wy * 64 + mi * 16 + h * 8 + er][wx] = m;
        }
    __syncthreads();
    if (t < 128)
        s_row[t] = fmaxf(fmaxf(s_red[t][0], s_red[t][1]), fmaxf(s_red[t][2], s_red[t][3]));
    __syncthreads();

    // per-tile row sumexp
#pragma unroll
    for (int mi = 0; mi < 4; mi++)
#pragma unroll
        for (int h = 0; h < 2; h++) {
            const float m = s_row[wy * 64 + mi * 16 + h * 8 + er];
            float s = 0.0f;
#pragma unroll
            for (int nj = 0; nj < 4; nj++)
                s += __expf(acc[mi][nj][h * 2] - m) + __expf(acc[mi][nj][h * 2 + 1] - m);
            s += __shfl_xor_sync(0xffffffffu, s, 1);
            s += __shfl_xor_sync(0xffffffffu, s, 2);
            if ((lane & 3) == 0) s_red[wy * 64 + mi * 16 + h * 8 + er][wx] = s;
        }
    __syncthreads();
    if (t < 128) {
        float s = s_red[t][0] + s_red[t][1] + s_red[t][2] + s_red[t][3];
        size_t row = (size_t)bh * S_ + q0 + t;
        g_st_max[row * 16 + kt] = s_row[t];
        g_st_sum[row * 16 + kt] = s;
    }

    // write raw scaled logits
#pragma unroll
    for (int mi = 0; mi < 4; mi++)
#pragma unroll
        for (int nj = 0; nj < 4; nj++) {
            const int col = k0 + wx * 32 + nj * 8 + ec;
            const int row0 = q0 + wy * 64 + mi * 16 + er;
#pragma unroll
            for (int h = 0; h < 2; h++) {
                float2 v = make_float2(acc[mi][nj][h * 2], acc[mi][nj][h * 2 + 1]);
                *(float2*)(Out + (size_t)(row0 + h * 8) * S_ + col) = v;
            }
        }
}

// ---------------- stats reduce ------------------------------------------------
__global__ void __launch_bounds__(256) stat_reduce()
{
    const int r = blockIdx.x * 256 + threadIdx.x;
    float m = -1e30f;
#pragma unroll
    for (int i = 0; i < 16; i++) m = fmaxf(m, g_st_max[(size_t)r * 16 + i]);
    float s = 0.0f;
#pragma unroll
    for (int i = 0; i < 16; i++)
        s += g_st_sum[(size_t)r * 16 + i] * __expf(g_st_max[(size_t)r * 16 + i] - m);
    g_row_m[r] = m;
    g_row_inv[r] = 1.0f / s;
}

// ---------------- attnv: inline softmax + p@V + write p ----------------------
// CTA 128q x 64d, 8 warps (32x32). chunk 64, double-buffered.
// smem: A buf0 @0 (AH 16K, AL 16K), A buf1 @32K; V buf0 @64K (VH 8K, VL 8K), buf1 @80K.
__global__ void __launch_bounds__(256, 1) attnv_tc(float* __restrict__ attn)
{
    extern __shared__ __align__(1024) char smp[];
    __shared__ float sm_m[128], sm_i[128];
    uint32_t sb = smem_u32(smp);
    const int t = threadIdx.x, lane = t & 31, wid = t >> 5;
    const int wy = wid >> 1, wx = wid & 1;
    const int bh = blockIdx.y, q0 = blockIdx.x * 128;
    float* A = attn + (size_t)bh * S_ * S_;
    const __nv_bfloat16* Vh = g_hd_h[2] + (size_t)bh * S_ * DH_;
    const __nv_bfloat16* Vl = g_hd_l[2] + (size_t)bh * S_ * DH_;

    if (t < 128) {
        size_t row = (size_t)bh * S_ + q0 + t;
        sm_m[t] = g_row_m[row];
        sm_i[t] = g_row_inv[row];
    }
    __syncthreads();

    float acc[2][4][4];
#pragma unroll
    for (int i = 0; i < 2; i++)
#pragma unroll
        for (int j = 0; j < 4; j++)
#pragma unroll
            for (int k = 0; k < 4; k++) acc[i][j][k] = 0.0f;

    float4 ra[8];
    const int arow = t >> 4, ac4 = t & 15;

#define AV_CPV(c) do { \
    const int kc_ = (c) * 64; \
    uint32_t vb_ = sb + 65536 + ((c) & 1) * 16384; \
    _Pragma("unroll") \
    for (int i_ = 0; i_ < 2; i_++) { \
        int e_ = i_ * 256 + t, r_ = e_ >> 3, c8_ = e_ & 7; \
        uint32_t so_ = r_ * 128 + ((c8_ ^ (r_ & 7)) << 4); \
        cp16(vb_ + so_,        Vh + (size_t)(kc_ + r_) * DH_ + c8_ * 8); \
        cp16(vb_ + 8192 + so_, Vl + (size_t)(kc_ + r_) * DH_ + c8_ * 8); \
    } \
    CP_COMMIT(); \
} while (0)

#define AV_LDA(c) do { \
    const int kc_ = (c) * 64; \
    _Pragma("unroll") \
    for (int i_ = 0; i_ < 8; i_++) \
        ra[i_] = *(const float4*)(A + (size_t)(q0 + i_ * 16 + arow) * S_ + kc_ + ac4 * 4); \
} while (0)

#define AV_STA(c) do { \
    const int kc_ = (c) * 64; \
    char* ab_ = smp + ((c) & 1) * 32768; \
    _Pragma("unroll") \
    for (int i_ = 0; i_ < 8; i_++) { \
        int r_ = i_ * 16 + arow; \
        const float m_ = sm_m[r_], in_ = sm_i[r_]; \
        float4 p_; \
        p_.x = __expf(ra[i_].x - m_) * in_; \
        p_.y = __expf(ra[i_].y - m_) * in_; \
        p_.z = __expf(ra[i_].z - m_) * in_; \
        p_.w = __expf(ra[i_].w - m_) * in_; \
        *(float4*)(A + (size_t)(q0 + r_) * S_ + kc_ + ac4 * 4) = p_; \
        uint32_t h01, l01, h23, l23; \
        split2(p_.x, p_.y, h01, l01); \
        split2(p_.z, p_.w, h23, l23); \
        uint32_t so_ = r_ * 128 + ((((ac4 >> 1) ^ (r_ & 7)) << 4)) + (ac4 & 1) * 8; \
        *(uint2*)(ab_ + so_)         = make_uint2(h01, h23); \
        *(uint2*)(ab_ + 16384 + so_) = make_uint2(l01, l23); \
    } \
} while (0)

#define AV_MMA(c) do { \
    uint32_t aAH = sb + ((c) & 1) * 32768, aAL = aAH + 16384; \
    uint32_t aBH = sb + 65536 + ((c) & 1) * 16384, aBL = aBH + 8192; \
    _Pragma("unroll") \
    for (int s = 0; s < 4; s++) { \
        const int rA0 = wy * 32 + ((lane >> 3) & 1) * 8 + (lane & 7); \
        const int cA = 2 * s + (lane >> 4); \
        uint32_t ah[2][4], al[2][4]; \
        _Pragma("unroll") \
        for (int mi = 0; mi < 2; mi++) { \
            int r = rA0 + mi * 16; \
            uint32_t off = r * 128 + ((cA ^ (r & 7)) << 4); \
            ldsm4(ah[mi], aAH + off); \
            ldsm4(al[mi], aAL + off); \
        } \
        const int rB = 16 * s + ((lane >> 3) & 1) * 8 + (lane & 7); \
        uint32_t bh2[2][4], bl2[2][4]; \
        _Pragma("unroll") \
        for (int nh = 0; nh < 2; nh++) { \
            int cB = ((wx * 32 + nh * 16) >> 3) + ((lane >> 4) & 1); \
            uint32_t off = rB * 128 + ((cB ^ (rB & 7)) << 4); \
            ldsm4t(bh2[nh], aBH + off); \
            ldsm4t(bl2[nh], aBL + off); \
        } \
        _Pragma("unroll") \
        for (int mi = 0; mi < 2; mi++) \
            _Pragma("unroll") \
            for (int nj = 0; nj < 4; nj++) { \
                uint32_t b0 = bh2[nj >> 1][(nj & 1) * 2], b1 = bh2[nj >> 1][(nj & 1) * 2 + 1]; \
                uint32_t c0 = bl2[nj >> 1][(nj & 1) * 2], c1 = bl2[nj >> 1][(nj & 1) * 2 + 1]; \
                mma_bf16(acc[mi][nj], ah[mi], b0, b1); \
                mma_bf16(acc[mi][nj], ah[mi], c0, c1); \
                mma_bf16(acc[mi][nj], al[mi], b0, b1); \
            } \
    } \
} while (0)

    AV_CPV(0);
    AV_LDA(0);
    AV_STA(0);
#pragma unroll 1
    for (int c = 0; c < 32; c++) {
        if (c + 1 < 32) { AV_CPV(c + 1); AV_LDA(c + 1); }
        if (c < 31) cp_wait<1>(); else cp_wait<0>();
        __syncthreads();
        AV_MMA(c);
        if (c + 1 < 32) AV_STA(c + 1);
        __syncthreads();
    }

    const int bb = bh >> 4, hh = bh & (H_ - 1);
    const int er = lane >> 2, ec = (lane & 3) * 2;
#pragma unroll
    for (int mi = 0; mi < 2; mi++)
#pragma unroll
        for (int nj = 0; nj < 4; nj++) {
            const int dd = wx * 32 + nj * 8 + ec;
            const int row0 = q0 + wy * 32 + mi * 16 + er;
#pragma unroll
            for (int h = 0; h < 2; h++) {
                const int ss = row0 + h * 8;
                uint32_t hv, lv;
                split2(acc[mi][nj][h * 2], acc[mi][nj][h * 2 + 1], hv, lv);
                size_t idx = ((size_t)(bb * S_ + ss)) * D_ + hh * DH_ + dd;
                *(uint32_t*)(g_cat_h + idx) = hv;
                *(uint32_t*)(g_cat_l + idx) = lv;
            }
        }
}

// ---------------- launch ------------------------------------------------------
extern "C" void kernel_launch(void* const* d_in, const int* in_sizes, int n_in,
                              void* d_out, int out_size)
{
    const float* q  = (const float*)d_in[0];
    const float* k  = (const float*)d_in[1];
    const float* v  = (const float*)d_in[2];
    const float* Wq = (const float*)d_in[3];
    const float* bq = (const float*)d_in[4];
    const float* Wk = (const float*)d_in[5];
    const float* bk = (const float*)d_in[6];
    const float* Wv = (const float*)d_in[7];
    const float* bv = (const float*)d_in[8];
    const float* Wc = (const float*)d_in[9];
    const float* bc = (const float*)d_in[10];

    float* out  = (float*)d_out;
    float* attn = out + OUT_ELEMS;

    const int SM_PROJ = 196608;
    const int SM_LOG  = 65536;
    const int SM_AV   = 98304;
    cudaFuncSetAttribute(proj_tc,   cudaFuncAttributeMaxDynamicSharedMemorySize, SM_PROJ);
    cudaFuncSetAttribute(logits_tc, cudaFuncAttributeMaxDynamicSharedMemorySize, SM_LOG);
    cudaFuncSetAttribute(attnv_tc,  cudaFuncAttributeMaxDynamicSharedMemorySize, SM_AV);

    split_all<<<16384, 256>>>(q, k, v, Wq, Wk, Wv, Wc);

    proj_tc<<<dim3(8, 32, 3), 256, SM_PROJ>>>(bq, bk, bv, bc, nullptr, 0);

    logits_tc<<<dim3(16, 16, 32), 256, SM_LOG>>>(attn);

    stat_reduce<<<256, 256>>>();

    attnv_tc<<<dim3(16, 32), 256, SM_AV>>>(attn);

    proj_tc<<<dim3(8, 32, 1), 256, SM_PROJ>>>(bq, bk, bv, bc, out, 3);
}

// round 5
// speedup vs baseline: 2.6114x; 1.0258x over previous
#include <cuda_runtime.h>
#include <cuda_bf16.h>
#include <math.h>
#include <stdint.h>

#define B_ 2
#define S_ 2048
#define D_ 1024
#define H_ 16
#define DH_ 64
#define NTOK 4096
#define OUT_ELEMS ((size_t)NTOK * D_)

// ---------------- pre-split bf16 hi/lo scratch -------------------------------
__device__ __nv_bfloat16 g_xs_h[3][(size_t)NTOK * D_];
__device__ __nv_bfloat16 g_xs_l[3][(size_t)NTOK * D_];
__device__ __nv_bfloat16 g_ws_h[4][(size_t)D_ * D_];
__device__ __nv_bfloat16 g_ws_l[4][(size_t)D_ * D_];
__device__ __nv_bfloat16 g_hd_h[3][(size_t)NTOK * D_];   // head-split q/k/v
__device__ __nv_bfloat16 g_hd_l[3][(size_t)NTOK * D_];
__device__ __nv_bfloat16 g_cat_h[(size_t)NTOK * D_];
__device__ __nv_bfloat16 g_cat_l[(size_t)NTOK * D_];

// ---------------- helpers -----------------------------------------------------
__device__ __forceinline__ uint32_t smem_u32(const void* p) {
    uint32_t a;
    asm("{ .reg .u64 t; cvta.to.shared.u64 t, %1; cvt.u32.u64 %0, t; }" : "=r"(a) : "l"(p));
    return a;
}
__device__ __forceinline__ void mma_bf16(float c[4], const uint32_t a[4],
                                         uint32_t b0, uint32_t b1) {
    asm volatile("mma.sync.aligned.m16n8k16.row.col.f32.bf16.bf16.f32 "
        "{%0,%1,%2,%3}, {%4,%5,%6,%7}, {%8,%9}, {%0,%1,%2,%3};"
        : "+f"(c[0]), "+f"(c[1]), "+f"(c[2]), "+f"(c[3])
        : "r"(a[0]), "r"(a[1]), "r"(a[2]), "r"(a[3]), "r"(b0), "r"(b1));
}
__device__ __forceinline__ void ldsm4(uint32_t r[4], uint32_t a) {
    asm volatile("ldmatrix.sync.aligned.m8n8.x4.shared.b16 {%0,%1,%2,%3}, [%4];"
        : "=r"(r[0]), "=r"(r[1]), "=r"(r[2]), "=r"(r[3]) : "r"(a));
}
__device__ __forceinline__ void ldsm4t(uint32_t r[4], uint32_t a) {
    asm volatile("ldmatrix.sync.aligned.m8n8.x4.trans.shared.b16 {%0,%1,%2,%3}, [%4];"
        : "=r"(r[0]), "=r"(r[1]), "=r"(r[2]), "=r"(r[3]) : "r"(a));
}
__device__ __forceinline__ void split2(float x, float y, uint32_t& hi, uint32_t& lo) {
    __nv_bfloat16 hx = __float2bfloat16(x), hy = __float2bfloat16(y);
    __nv_bfloat16 lx = __float2bfloat16(x - __bfloat162float(hx));
    __nv_bfloat16 ly = __float2bfloat16(y - __bfloat162float(hy));
    __nv_bfloat162 h(hx, hy), l(lx, ly);
    hi = *(uint32_t*)&h;
    lo = *(uint32_t*)&l;
}
__device__ __forceinline__ void cp16(uint32_t smem, const void* g) {
    asm volatile("cp.async.cg.shared.global [%0], [%1], 16;" :: "r"(smem), "l"(g));
}
#define CP_COMMIT() asm volatile("cp.async.commit_group;" ::: "memory")
template<int N> __device__ __forceinline__ void cp_wait() {
    asm volatile("cp.async.wait_group %0;" :: "n"(N) : "memory");
}

// ---------------- prep: split inputs + weights --------------------------------
__global__ void __launch_bounds__(256) split_all(
    const float* __restrict__ q, const float* __restrict__ k, const float* __restrict__ v,
    const float* __restrict__ wq, const float* __restrict__ wk,
    const float* __restrict__ wv, const float* __restrict__ wc)
{
    int i = blockIdx.x * 256 + threadIdx.x;          // float4 index
    const float* src;
    __nv_bfloat16 *dh, *dl;
    int off;
    if (i < 3 * 1048576) {
        int ti = i >> 20; off = i & 1048575;
        src = (ti == 0) ? q : (ti == 1) ? k : v;
        dh = g_xs_h[ti]; dl = g_xs_l[ti];
    } else {
        int j = i - 3145728;
        int ti = j >> 18; off = j & 262143;
        src = (ti == 0) ? wq : (ti == 1) ? wk : (ti == 2) ? wv : wc;
        dh = g_ws_h[ti]; dl = g_ws_l[ti];
    }
    float4 x = ((const float4*)src)[off];
    uint32_t h01, l01, h23, l23;
    split2(x.x, x.y, h01, l01);
    split2(x.z, x.w, h23, l23);
    ((uint2*)dh)[off] = make_uint2(h01, h23);
    ((uint2*)dl)[off] = make_uint2(l01, l23);
}

// ---------------- projection GEMM (cp.async, 3-stage) -------------------------
__global__ void __launch_bounds__(256, 1)
proj_tc(const float* __restrict__ bq, const float* __restrict__ bk,
        const float* __restrict__ bv, const float* __restrict__ bc,
        float* __restrict__ Yout, int mode_base)
{
    extern __shared__ __align__(1024) char smp[];
    uint32_t sb = smem_u32(smp);
    const int t = threadIdx.x, lane = t & 31, wid = t >> 5;
    const int wy = wid >> 2, wx = wid & 3;
    const int mode = mode_base + blockIdx.z;
    const __nv_bfloat16 *Xh, *Xl;
    if (mode < 3) { Xh = g_xs_h[mode]; Xl = g_xs_l[mode]; }
    else          { Xh = g_cat_h;      Xl = g_cat_l; }
    const __nv_bfloat16 *Wh = g_ws_h[mode], *Wl = g_ws_l[mode];
    const float* bias = (mode == 0) ? bq : (mode == 1) ? bk : (mode == 2) ? bv : bc;
    const int bm = blockIdx.y * 128, bn = blockIdx.x * 128;

    float acc[4][4][4];
#pragma unroll
    for (int i = 0; i < 4; i++)
#pragma unroll
        for (int j = 0; j < 4; j++)
#pragma unroll
            for (int k = 0; k < 4; k++) acc[i][j][k] = 0.0f;

#define PJ_PF(c) do { \
    const int kc_ = (c) * 64; \
    uint32_t bo_ = sb + ((c) % 3) * 65536; \
    _Pragma("unroll") \
    for (int i_ = 0; i_ < 4; i_++) { \
        int e_ = i_ * 256 + t, r_ = e_ >> 3, c8_ = e_ & 7; \
        uint32_t so_ = r_ * 128 + ((c8_ ^ (r_ & 7)) << 4); \
        const size_t g_ = (size_t)(bm + r_) * D_ + kc_ + c8_ * 8; \
        cp16(bo_ + so_,         Xh + g_); \
        cp16(bo_ + 16384 + so_, Xl + g_); \
    } \
    _Pragma("unroll") \
    for (int i_ = 0; i_ < 4; i_++) { \
        int e_ = i_ * 256 + t, k_ = e_ >> 4, b_ = e_ & 15; \
        uint32_t so_ = k_ * 256 + ((b_ ^ (k_ & 7)) << 4); \
        const size_t g_ = (size_t)(kc_ + k_) * D_ + bn + b_ * 8; \
        cp16(bo_ + 32768 + so_, Wh + g_); \
        cp16(bo_ + 49152 + so_, Wl + g_); \
    } \
    CP_COMMIT(); \
} while (0)

#define PJ_MMA(base) do { \
    uint32_t aAH = (base), aAL = (base) + 16384, aBH = (base) + 32768, aBL = (base) + 49152; \
    _Pragma("unroll") \
    for (int s = 0; s < 4; s++) { \
        const int rA0 = wy * 64 + ((lane >> 3) & 1) * 8 + (lane & 7); \
        const int cA = 2 * s + (lane >> 4); \
        uint32_t ah[4][4], al[4][4]; \
        _Pragma("unroll") \
        for (int mi = 0; mi < 4; mi++) { \
            int r = rA0 + mi * 16; \
            uint32_t off = r * 128 + ((cA ^ (r & 7)) << 4); \
            ldsm4(ah[mi], aAH + off); \
            ldsm4(al[mi], aAL + off); \
        } \
        const int rB = 16 * s + ((lane >> 3) & 1) * 8 + (lane & 7); \
        uint32_t bh[2][4], bl[2][4]; \
        _Pragma("unroll") \
        for (int nh = 0; nh < 2; nh++) { \
            int cB = ((wx * 32 + nh * 16) >> 3) + ((lane >> 4) & 1); \
            uint32_t off = rB * 256 + ((cB ^ (rB & 7)) << 4); \
            ldsm4t(bh[nh], aBH + off); \
            ldsm4t(bl[nh], aBL + off); \
        } \
        _Pragma("unroll") \
        for (int mi = 0; mi < 4; mi++) \
            _Pragma("unroll") \
            for (int nj = 0; nj < 4; nj++) { \
                uint32_t bh0 = bh[nj >> 1][(nj & 1) * 2], bh1 = bh[nj >> 1][(nj & 1) * 2 + 1]; \
                uint32_t bl0 = bl[nj >> 1][(nj & 1) * 2], bl1 = bl[nj >> 1][(nj & 1) * 2 + 1]; \
                mma_bf16(acc[mi][nj], ah[mi], bh0, bh1); \
                mma_bf16(acc[mi][nj], ah[mi], bl0, bl1); \
                mma_bf16(acc[mi][nj], al[mi], bh0, bh1); \
            } \
    } \
} while (0)

    PJ_PF(0); PJ_PF(1);
#pragma unroll 1
    for (int c = 0; c < 16; c++) {
        if (c + 2 < 16) PJ_PF(c + 2);
        if (c < 14) cp_wait<2>(); else if (c == 14) cp_wait<1>(); else cp_wait<0>();
        __syncthreads();
        PJ_MMA(sb + (c % 3) * 65536);
        __syncthreads();
    }

    const int er = lane >> 2, ec = (lane & 3) * 2;
    if (mode < 3) {
        __nv_bfloat16* dh = g_hd_h[mode];
        __nv_bfloat16* dl = g_hd_l[mode];
#pragma unroll
        for (int mi = 0; mi < 4; mi++)
#pragma unroll
            for (int nj = 0; nj < 4; nj++) {
                const int col = bn + wx * 32 + nj * 8 + ec;
                const float b0 = __ldg(bias + col), b1 = __ldg(bias + col + 1);
                const int row0 = bm + wy * 64 + mi * 16 + er;
#pragma unroll
                for (int h = 0; h < 2; h++) {
                    const int row = row0 + h * 8;
                    uint32_t hv, lv;
                    split2(acc[mi][nj][h * 2] + b0, acc[mi][nj][h * 2 + 1] + b1, hv, lv);
                    int bb = row >> 11, ss = row & (S_ - 1), hh = col >> 6, dd = col & (DH_ - 1);
                    size_t idx = (((size_t)(bb * H_ + hh)) * S_ + ss) * DH_ + dd;
                    *(uint32_t*)(dh + idx) = hv;
                    *(uint32_t*)(dl + idx) = lv;
                }
            }
    } else {
#pragma unroll
        for (int mi = 0; mi < 4; mi++)
#pragma unroll
            for (int nj = 0; nj < 4; nj++) {
                const int col = bn + wx * 32 + nj * 8 + ec;
                const float b0 = __ldg(bias + col), b1 = __ldg(bias + col + 1);
                const int row0 = bm + wy * 64 + mi * 16 + er;
#pragma unroll
                for (int h = 0; h < 2; h++) {
                    float2 v = make_float2(acc[mi][nj][h * 2] + b0, acc[mi][nj][h * 2 + 1] + b1);
                    *(float2*)(Yout + (size_t)(row0 + h * 8) * D_ + col) = v;
                }
            }
    }
}

// ---------------- fused attention: logits + softmax + p@V --------------------
// One CTA per (bh, 128-q-tile).  SMEM (96KB):
//  pass1: Q @0 (hi 16K, lo 16K); K buf0 @32K, K buf1 @64K (hi 16K, lo 16K each)
//  pass2: P buf0 @0, P buf1 @32K (hi 16K, lo 16K); V buf0 @64K (hi 8K, lo 8K), V buf1 @80K
__global__ void __launch_bounds__(256, 2) fused_attn(float* __restrict__ attn)
{
    extern __shared__ __align__(1024) char smp[];
    __shared__ float s_red[128][4];
    __shared__ float s_row[128];
    __shared__ float sm_m[128], sm_s[128], sm_i[128];
    uint32_t sb = smem_u32(smp);
    const int t = threadIdx.x, lane = t & 31, wid = t >> 5;
    const int bh = blockIdx.y, q0 = blockIdx.x * 128;
    const __nv_bfloat16* Qh = g_hd_h[0] + (size_t)bh * S_ * DH_;
    const __nv_bfloat16* Ql = g_hd_l[0] + (size_t)bh * S_ * DH_;
    const __nv_bfloat16* Kh = g_hd_h[1] + (size_t)bh * S_ * DH_;
    const __nv_bfloat16* Kl = g_hd_l[1] + (size_t)bh * S_ * DH_;
    const __nv_bfloat16* Vh = g_hd_h[2] + (size_t)bh * S_ * DH_;
    const __nv_bfloat16* Vl = g_hd_l[2] + (size_t)bh * S_ * DH_;
    float* A = attn + (size_t)bh * S_ * S_;

    if (t < 128) { sm_m[t] = -1e30f; sm_s[t] = 0.0f; }

    // ---- load Q (group with K0) ----
#pragma unroll
    for (int i = 0; i < 4; i++) {
        int e = i * 256 + t, r = e >> 3, c8 = e & 7;
        uint32_t so = r * 128 + ((c8 ^ (r & 7)) << 4);
        cp16(sb + so,         Qh + (size_t)(q0 + r) * DH_ + c8 * 8);
        cp16(sb + 16384 + so, Ql + (size_t)(q0 + r) * DH_ + c8 * 8);
    }
#define FA_KPF(kt) do { \
    uint32_t kb_ = sb + 32768 + ((kt) & 1) * 32768; \
    _Pragma("unroll") \
    for (int i_ = 0; i_ < 4; i_++) { \
        int e_ = i_ * 256 + t, r_ = e_ >> 3, c8_ = e_ & 7; \
        uint32_t so_ = r_ * 128 + ((c8_ ^ (r_ & 7)) << 4); \
        cp16(kb_ + so_,         Kh + (size_t)((kt) * 128 + r_) * DH_ + c8_ * 8); \
        cp16(kb_ + 16384 + so_, Kl + (size_t)((kt) * 128 + r_) * DH_ + c8_ * 8); \
    } \
    CP_COMMIT(); \
} while (0)

    FA_KPF(0);          // group0 = Q + K0
    FA_KPF(1);          // group1 = K1

    // ================= PASS 1: S = 0.125 * Q K^T, online stats =================
    {
        const int wy = wid >> 2, wx = wid & 3;       // 2 x 4 warps, warp 64q x 32k
        const int er = lane >> 2, ec = (lane & 3) * 2;
#pragma unroll 1
        for (int kt = 0; kt < 16; kt++) {
            if (kt == 15) cp_wait<0>(); else cp_wait<1>();
            __syncthreads();

            float acc[4][4][4];
#pragma unroll
            for (int i = 0; i < 4; i++)
#pragma unroll
                for (int j = 0; j < 4; j++)
#pragma unroll
                    for (int k = 0; k < 4; k++) acc[i][j][k] = 0.0f;

            const uint32_t aQH = sb, aQL = sb + 16384;
            const uint32_t aKH = sb + 32768 + (kt & 1) * 32768, aKL = aKH + 16384;
#pragma unroll
            for (int s = 0; s < 4; s++) {
                const int rA0 = wy * 64 + ((lane >> 3) & 1) * 8 + (lane & 7);
                const int cA = 2 * s + (lane >> 4);
                uint32_t ah[4][4], al[4][4];
#pragma unroll
                for (int mi = 0; mi < 4; mi++) {
                    int r = rA0 + mi * 16;
                    uint32_t off = r * 128 + ((cA ^ (r & 7)) << 4);
                    ldsm4(ah[mi], aQH + off);
                    ldsm4(al[mi], aQL + off);
                }
                uint32_t bhf[2][4], blf[2][4];
                const int cB = 2 * s + ((lane >> 3) & 1);
#pragma unroll
                for (int nh = 0; nh < 2; nh++) {
                    int r = wx * 32 + nh * 16 + ((lane >> 4) & 1) * 8 + (lane & 7);
                    uint32_t off = r * 128 + ((cB ^ (r & 7)) << 4);
                    ldsm4(bhf[nh], aKH + off);
                    ldsm4(blf[nh], aKL + off);
                }
#pragma unroll
                for (int mi = 0; mi < 4; mi++)
#pragma unroll
                    for (int nj = 0; nj < 4; nj++) {
                        uint32_t b0 = bhf[nj >> 1][(nj & 1) * 2], b1 = bhf[nj >> 1][(nj & 1) * 2 + 1];
                        uint32_t c0 = blf[nj >> 1][(nj & 1) * 2], c1 = blf[nj >> 1][(nj & 1) * 2 + 1];
                        mma_bf16(acc[mi][nj], ah[mi], b0, b1);
                        mma_bf16(acc[mi][nj], ah[mi], c0, c1);
                        mma_bf16(acc[mi][nj], al[mi], b0, b1);
                    }
            }
#pragma unroll
            for (int i = 0; i < 4; i++)
#pragma unroll
                for (int j = 0; j < 4; j++)
#pragma unroll
                    for (int k = 0; k < 4; k++) acc[i][j][k] *= 0.125f;

            __syncthreads();   // protect s_red/s_row reuse across tiles
            // tile row max
#pragma unroll
            for (int mi = 0; mi < 4; mi++)
#pragma unroll
                for (int h = 0; h < 2; h++) {
                    float m = -1e30f;
#pragma unroll
                    for (int nj = 0; nj < 4; nj++)
                        m = fmaxf(m, fmaxf(acc[mi][nj][h * 2], acc[mi][nj][h * 2 + 1]));
                    m = fmaxf(m, __shfl_xor_sync(0xffffffffu, m, 1));
                    m = fmaxf(m, __shfl_xor_sync(0xffffffffu, m, 2));
                    if ((lane & 3) == 0) s_red[wy * 64 + mi * 16 + h * 8 + er][wx] = m;
                }
            __syncthreads();
            if (t < 128)
                s_row[t] = fmaxf(fmaxf(s_red[t][0], s_red[t][1]),
                                 fmaxf(s_red[t][2], s_red[t][3]));
            __syncthreads();
            // tile row sumexp
#pragma unroll
            for (int mi = 0; mi < 4; mi++)
#pragma unroll
                for (int h = 0; h < 2; h++) {
                    const float m = s_row[wy * 64 + mi * 16 + h * 8 + er];
                    float s = 0.0f;
#pragma unroll
                    for (int nj = 0; nj < 4; nj++)
                        s += __expf(acc[mi][nj][h * 2] - m) + __expf(acc[mi][nj][h * 2 + 1] - m);
                    s += __shfl_xor_sync(0xffffffffu, s, 1);
                    s += __shfl_xor_sync(0xffffffffu, s, 2);
                    if ((lane & 3) == 0) s_red[wy * 64 + mi * 16 + h * 8 + er][wx] = s;
                }
            __syncthreads();
            if (t < 128) {
                float st = s_red[t][0] + s_red[t][1] + s_red[t][2] + s_red[t][3];
                float mt = s_row[t];
                float mo = sm_m[t];
                float mn = fmaxf(mo, mt);
                sm_s[t] = sm_s[t] * __expf(mo - mn) + st * __expf(mt - mn);
                sm_m[t] = mn;
            }
            // write raw S tile
            const int k0 = kt * 128;
#pragma unroll
            for (int mi = 0; mi < 4; mi++)
#pragma unroll
                for (int nj = 0; nj < 4; nj++) {
                    const int col = k0 + wx * 32 + nj * 8 + ec;
                    const int row0 = q0 + wy * 64 + mi * 16 + er;
#pragma unroll
                    for (int h = 0; h < 2; h++) {
                        float2 v = make_float2(acc[mi][nj][h * 2], acc[mi][nj][h * 2 + 1]);
                        *(float2*)(A + (size_t)(row0 + h * 8) * S_ + col) = v;
                    }
                }
            __syncthreads();
            if (kt + 2 < 16) FA_KPF(kt + 2);
        }
    }
    __syncthreads();
    if (t < 128) sm_i[t] = 1.0f / sm_s[t];
    __syncthreads();

    // ================= PASS 2: p = exp(S-m)*inv ; O = p @ V ====================
    {
        const int wy = wid >> 1, wx = wid & 1;       // 4 x 2 warps, warp 32q x 32d
        float acc[2][4][4];
#pragma unroll
        for (int i = 0; i < 2; i++)
#pragma unroll
            for (int j = 0; j < 4; j++)
#pragma unroll
                for (int k = 0; k < 4; k++) acc[i][j][k] = 0.0f;

        float4 ra[8];
        const int arow = t >> 4, ac4 = t & 15;

#define FA_VPF(c) do { \
    const int kc_ = (c) * 64; \
    uint32_t vb_ = sb + 65536 + ((c) & 1) * 16384; \
    _Pragma("unroll") \
    for (int i_ = 0; i_ < 2; i_++) { \
        int e_ = i_ * 256 + t, r_ = e_ >> 3, c8_ = e_ & 7; \
        uint32_t so_ = r_ * 128 + ((c8_ ^ (r_ & 7)) << 4); \
        cp16(vb_ + so_,        Vh + (size_t)(kc_ + r_) * DH_ + c8_ * 8); \
        cp16(vb_ + 8192 + so_, Vl + (size_t)(kc_ + r_) * DH_ + c8_ * 8); \
    } \
    CP_COMMIT(); \
} while (0)

#define FA_LDA(c) do { \
    const int kc_ = (c) * 64; \
    _Pragma("unroll") \
    for (int i_ = 0; i_ < 8; i_++) \
        ra[i_] = *(const float4*)(A + (size_t)(q0 + i_ * 16 + arow) * S_ + kc_ + ac4 * 4); \
} while (0)

#define FA_STA(c) do { \
    const int kc_ = (c) * 64; \
    char* ab_ = smp + ((c) & 1) * 32768; \
    _Pragma("unroll") \
    for (int i_ = 0; i_ < 8; i_++) { \
        int r_ = i_ * 16 + arow; \
        const float m_ = sm_m[r_], in_ = sm_i[r_]; \
        float4 p_; \
        p_.x = __expf(ra[i_].x - m_) * in_; \
        p_.y = __expf(ra[i_].y - m_) * in_; \
        p_.z = __expf(ra[i_].z - m_) * in_; \
        p_.w = __expf(ra[i_].w - m_) * in_; \
        *(float4*)(A + (size_t)(q0 + r_) * S_ + kc_ + ac4 * 4) = p_; \
        uint32_t h01, l01, h23, l23; \
        split2(p_.x, p_.y, h01, l01); \
        split2(p_.z, p_.w, h23, l23); \
        uint32_t so_ = r_ * 128 + ((((ac4 >> 1) ^ (r_ & 7)) << 4)) + (ac4 & 1) * 8; \
        *(uint2*)(ab_ + so_)         = make_uint2(h01, h23); \
        *(uint2*)(ab_ + 16384 + so_) = make_uint2(l01, l23); \
    } \
} while (0)

#define FA_MMA(c) do { \
    uint32_t aAH = sb + ((c) & 1) * 32768, aAL = aAH + 16384; \
    uint32_t aBH = sb + 65536 + ((c) & 1) * 16384, aBL = aBH + 8192; \
    _Pragma("unroll") \
    for (int s = 0; s < 4; s++) { \
        const int rA0 = wy * 32 + ((lane >> 3) & 1) * 8 + (lane & 7); \
        const int cA = 2 * s + (lane >> 4); \
        uint32_t ah[2][4], al[2][4]; \
        _Pragma("unroll") \
        for (int mi = 0; mi < 2; mi++) { \
            int r = rA0 + mi * 16; \
            uint32_t off = r * 128 + ((cA ^ (r & 7)) << 4); \
            ldsm4(ah[mi], aAH + off); \
            ldsm4(al[mi], aAL + off); \
        } \
        const int rB = 16 * s + ((lane >> 3) & 1) * 8 + (lane & 7); \
        uint32_t bh2[2][4], bl2[2][4]; \
        _Pragma("unroll") \
        for (int nh = 0; nh < 2; nh++) { \
            int cB = ((wx * 32 + nh * 16) >> 3) + ((lane >> 4) & 1); \
            uint32_t off = rB * 128 + ((cB ^ (rB & 7)) << 4); \
            ldsm4t(bh2[nh], aBH + off); \
            ldsm4t(bl2[nh], aBL + off); \
        } \
        _Pragma("unroll") \
        for (int mi = 0; mi < 2; mi++) \
            _Pragma("unroll") \
            for (int nj = 0; nj < 4; nj++) { \
                uint32_t b0 = bh2[nj >> 1][(nj & 1) * 2], b1 = bh2[nj >> 1][(nj & 1) * 2 + 1]; \
                uint32_t c0 = bl2[nj >> 1][(nj & 1) * 2], c1 = bl2[nj >> 1][(nj & 1) * 2 + 1]; \
                mma_bf16(acc[mi][nj], ah[mi], b0, b1); \
                mma_bf16(acc[mi][nj], ah[mi], c0, c1); \
                mma_bf16(acc[mi][nj], al[mi], b0, b1); \
            } \
    } \
} while (0)

        // reverse order: most recently written S tiles are read first (L2 warm)
        FA_VPF(31);
        FA_LDA(31);
        FA_STA(31);
#pragma unroll 1
        for (int c = 31; c >= 0; c--) {
            if (c > 0) { FA_VPF(c - 1); FA_LDA(c - 1); }
            if (c > 0) cp_wait<1>(); else cp_wait<0>();
            __syncthreads();
            FA_MMA(c);
            if (c > 0) FA_STA(c - 1);
            __syncthreads();
        }

        const int bb = bh >> 4, hh = bh & (H_ - 1);
        const int er = lane >> 2, ec = (lane & 3) * 2;
#pragma unroll
        for (int mi = 0; mi < 2; mi++)
#pragma unroll
            for (int nj = 0; nj < 4; nj++) {
                const int dd = wx * 32 + nj * 8 + ec;
                const int row0 = q0 + wy * 32 + mi * 16 + er;
#pragma unroll
                for (int h = 0; h < 2; h++) {
                    const int ss = row0 + h * 8;
                    uint32_t hv, lv;
                    split2(acc[mi][nj][h * 2], acc[mi][nj][h * 2 + 1], hv, lv);
                    size_t idx = ((size_t)(bb * S_ + ss)) * D_ + hh * DH_ + dd;
                    *(uint32_t*)(g_cat_h + idx) = hv;
                    *(uint32_t*)(g_cat_l + idx) = lv;
                }
            }
    }
}

// ---------------- launch ------------------------------------------------------
extern "C" void kernel_launch(void* const* d_in, const int* in_sizes, int n_in,
                              void* d_out, int out_size)
{
    const float* q  = (const float*)d_in[0];
    const float* k  = (const float*)d_in[1];
    const float* v  = (const float*)d_in[2];
    const float* Wq = (const float*)d_in[3];
    const float* bq = (const float*)d_in[4];
    const float* Wk = (const float*)d_in[5];
    const float* bk = (const float*)d_in[6];
    const float* Wv = (const float*)d_in[7];
    const float* bv = (const float*)d_in[8];
    const float* Wc = (const float*)d_in[9];
    const float* bc = (const float*)d_in[10];

    float* out  = (float*)d_out;
    float* attn = out + OUT_ELEMS;

    const int SM_PROJ = 196608;
    const int SM_FA   = 98304;
    cudaFuncSetAttribute(proj_tc,    cudaFuncAttributeMaxDynamicSharedMemorySize, SM_PROJ);
    cudaFuncSetAttribute(fused_attn, cudaFuncAttributeMaxDynamicSharedMemorySize, SM_FA);

    split_all<<<16384, 256>>>(q, k, v, Wq, Wk, Wv, Wc);

    proj_tc<<<dim3(8, 32, 3), 256, SM_PROJ>>>(bq, bk, bv, bc, nullptr, 0);

    fused_attn<<<dim3(16, 32), 256, SM_FA>>>(attn);

    proj_tc<<<dim3(8, 32, 1), 256, SM_PROJ>>>(bq, bk, bv, bc, out, 3);
}

// round 7
// speedup vs baseline: 2.6306x; 1.0074x over previous
#include <cuda_runtime.h>
#include <cuda_bf16.h>
#include <math.h>
#include <stdint.h>

#define B_ 2
#define S_ 2048
#define D_ 1024
#define H_ 16
#define DH_ 64
#define NTOK 4096
#define OUT_ELEMS ((size_t)NTOK * D_)

// ---------------- pre-split bf16 hi/lo scratch -------------------------------
__device__ __nv_bfloat16 g_xs_h[3][(size_t)NTOK * D_];
__device__ __nv_bfloat16 g_xs_l[3][(size_t)NTOK * D_];
__device__ __nv_bfloat16 g_ws_h[4][(size_t)D_ * D_];
__device__ __nv_bfloat16 g_ws_l[4][(size_t)D_ * D_];
__device__ __nv_bfloat16 g_hd_h[3][(size_t)NTOK * D_];   // head-split q/k/v
__device__ __nv_bfloat16 g_hd_l[3][(size_t)NTOK * D_];
__device__ __nv_bfloat16 g_cat_h[(size_t)NTOK * D_];
__device__ __nv_bfloat16 g_cat_l[(size_t)NTOK * D_];

// ---------------- helpers -----------------------------------------------------
__device__ __forceinline__ uint32_t smem_u32(const void* p) {
    uint32_t a;
    asm("{ .reg .u64 t; cvta.to.shared.u64 t, %1; cvt.u32.u64 %0, t; }" : "=r"(a) : "l"(p));
    return a;
}
__device__ __forceinline__ void mma_bf16(float c[4], const uint32_t a[4],
                                         uint32_t b0, uint32_t b1) {
    asm volatile("mma.sync.aligned.m16n8k16.row.col.f32.bf16.bf16.f32 "
        "{%0,%1,%2,%3}, {%4,%5,%6,%7}, {%8,%9}, {%0,%1,%2,%3};"
        : "+f"(c[0]), "+f"(c[1]), "+f"(c[2]), "+f"(c[3])
        : "r"(a[0]), "r"(a[1]), "r"(a[2]), "r"(a[3]), "r"(b0), "r"(b1));
}
__device__ __forceinline__ void ldsm4(uint32_t r[4], uint32_t a) {
    asm volatile("ldmatrix.sync.aligned.m8n8.x4.shared.b16 {%0,%1,%2,%3}, [%4];"
        : "=r"(r[0]), "=r"(r[1]), "=r"(r[2]), "=r"(r[3]) : "r"(a));
}
__device__ __forceinline__ void ldsm4t(uint32_t r[4], uint32_t a) {
    asm volatile("ldmatrix.sync.aligned.m8n8.x4.trans.shared.b16 {%0,%1,%2,%3}, [%4];"
        : "=r"(r[0]), "=r"(r[1]), "=r"(r[2]), "=r"(r[3]) : "r"(a));
}
__device__ __forceinline__ void split2(float x, float y, uint32_t& hi, uint32_t& lo) {
    __nv_bfloat16 hx = __float2bfloat16(x), hy = __float2bfloat16(y);
    __nv_bfloat16 lx = __float2bfloat16(x - __bfloat162float(hx));
    __nv_bfloat16 ly = __float2bfloat16(y - __bfloat162float(hy));
    __nv_bfloat162 h(hx, hy), l(lx, ly);
    hi = *(uint32_t*)&h;
    lo = *(uint32_t*)&l;
}
__device__ __forceinline__ void cp16(uint32_t smem, const void* g) {
    asm volatile("cp.async.cg.shared.global [%0], [%1], 16;" :: "r"(smem), "l"(g));
}
#define CP_COMMIT() asm volatile("cp.async.commit_group;" ::: "memory")
template<int N> __device__ __forceinline__ void cp_wait() {
    asm volatile("cp.async.wait_group %0;" :: "n"(N) : "memory");
}

// ---------------- prep: split inputs + weights --------------------------------
__global__ void __launch_bounds__(256) split_all(
    const float* __restrict__ q, const float* __restrict__ k, const float* __restrict__ v,
    const float* __restrict__ wq, const float* __restrict__ wk,
    const float* __restrict__ wv, const float* __restrict__ wc)
{
    int i = blockIdx.x * 256 + threadIdx.x;          // float4 index
    const float* src;
    __nv_bfloat16 *dh, *dl;
    int off;
    if (i < 3 * 1048576) {
        int ti = i >> 20; off = i & 1048575;
        src = (ti == 0) ? q : (ti == 1) ? k : v;
        dh = g_xs_h[ti]; dl = g_xs_l[ti];
    } else {
        int j = i - 3145728;
        int ti = j >> 18; off = j & 262143;
        src = (ti == 0) ? wq : (ti == 1) ? wk : (ti == 2) ? wv : wc;
        dh = g_ws_h[ti]; dl = g_ws_l[ti];
    }
    float4 x = ((const float4*)src)[off];
    uint32_t h01, l01, h23, l23;
    split2(x.x, x.y, h01, l01);
    split2(x.z, x.w, h23, l23);
    ((uint2*)dh)[off] = make_uint2(h01, h23);
    ((uint2*)dl)[off] = make_uint2(l01, l23);
}

// ---------------- projection GEMM: K-chunk 32, 3-stage, 2 CTAs/SM -------------
// CTA 128x128, 8 warps (64x32). stage 32KB: AH 0, AL 8K, BH 16K, BL 24K.
__global__ void __launch_bounds__(256, 2)
proj_tc(const float* __restrict__ bq, const float* __restrict__ bk,
        const float* __restrict__ bv, const float* __restrict__ bc,
        float* __restrict__ Yout, int mode_base)
{
    extern __shared__ __align__(1024) char smp[];
    uint32_t sb = smem_u32(smp);
    const int t = threadIdx.x, lane = t & 31, wid = t >> 5;
    const int wy = wid >> 2, wx = wid & 3;
    const int mode = mode_base + blockIdx.z;
    const __nv_bfloat16 *Xh, *Xl;
    if (mode < 3) { Xh = g_xs_h[mode]; Xl = g_xs_l[mode]; }
    else          { Xh = g_cat_h;      Xl = g_cat_l; }
    const __nv_bfloat16 *Wh = g_ws_h[mode], *Wl = g_ws_l[mode];
    const float* bias = (mode == 0) ? bq : (mode == 1) ? bk : (mode == 2) ? bv : bc;
    const int bm = blockIdx.y * 128, bn = blockIdx.x * 128;

    float acc[4][4][4];
#pragma unroll
    for (int i = 0; i < 4; i++)
#pragma unroll
        for (int j = 0; j < 4; j++)
#pragma unroll
            for (int k = 0; k < 4; k++) acc[i][j][k] = 0.0f;

#define PJ_PF(c) do { \
    const int kc_ = (c) * 32; \
    uint32_t bo_ = sb + ((c) % 3) * 32768; \
    _Pragma("unroll") \
    for (int i_ = 0; i_ < 2; i_++) { \
        int e_ = i_ * 256 + t, r_ = e_ >> 2, c8_ = e_ & 3; \
        uint32_t so_ = r_ * 64 + ((c8_ ^ (r_ & 3)) << 4); \
        const size_t g_ = (size_t)(bm + r_) * D_ + kc_ + c8_ * 8; \
        cp16(bo_ + so_,        Xh + g_); \
        cp16(bo_ + 8192 + so_, Xl + g_); \
    } \
    _Pragma("unroll") \
    for (int i_ = 0; i_ < 2; i_++) { \
        int e_ = i_ * 256 + t, k_ = e_ >> 4, b_ = e_ & 15; \
        uint32_t so_ = k_ * 256 + ((b_ ^ (k_ & 7)) << 4); \
        const size_t g_ = (size_t)(kc_ + k_) * D_ + bn + b_ * 8; \
        cp16(bo_ + 16384 + so_, Wh + g_); \
        cp16(bo_ + 24576 + so_, Wl + g_); \
    } \
    CP_COMMIT(); \
} while (0)

#define PJ_MMA(base) do { \
    uint32_t aAH = (base), aAL = (base) + 8192, aBH = (base) + 16384, aBL = (base) + 24576; \
    _Pragma("unroll") \
    for (int s = 0; s < 2; s++) { \
        const int rA0 = wy * 64 + ((lane >> 3) & 1) * 8 + (lane & 7); \
        const int cA = 2 * s + (lane >> 4); \
        uint32_t ah[4][4], al[4][4]; \
        _Pragma("unroll") \
        for (int mi = 0; mi < 4; mi++) { \
            int r = rA0 + mi * 16; \
            uint32_t off = r * 64 + ((cA ^ (r & 3)) << 4); \
            ldsm4(ah[mi], aAH + off); \
            ldsm4(al[mi], aAL + off); \
        } \
        const int rB = 16 * s + ((lane >> 3) & 1) * 8 + (lane & 7); \
        uint32_t bh[2][4], bl[2][4]; \
        _Pragma("unroll") \
        for (int nh = 0; nh < 2; nh++) { \
            int cB = ((wx * 32 + nh * 16) >> 3) + ((lane >> 4) & 1); \
            uint32_t off = rB * 256 + ((cB ^ (rB & 7)) << 4); \
            ldsm4t(bh[nh], aBH + off); \
            ldsm4t(bl[nh], aBL + off); \
        } \
        _Pragma("unroll") \
        for (int mi = 0; mi < 4; mi++) \
            _Pragma("unroll") \
            for (int nj = 0; nj < 4; nj++) { \
                uint32_t bh0 = bh[nj >> 1][(nj & 1) * 2], bh1 = bh[nj >> 1][(nj & 1) * 2 + 1]; \
                uint32_t bl0 = bl[nj >> 1][(nj & 1) * 2], bl1 = bl[nj >> 1][(nj & 1) * 2 + 1]; \
                mma_bf16(acc[mi][nj], ah[mi], bh0, bh1); \
                mma_bf16(acc[mi][nj], ah[mi], bl0, bl1); \
                mma_bf16(acc[mi][nj], al[mi], bh0, bh1); \
            } \
    } \
} while (0)

    PJ_PF(0); PJ_PF(1);
#pragma unroll 1
    for (int c = 0; c < 32; c++) {
        if (c + 2 < 32) PJ_PF(c + 2);
        if (c < 30) cp_wait<2>(); else if (c == 30) cp_wait<1>(); else cp_wait<0>();
        __syncthreads();
        PJ_MMA(sb + (c % 3) * 32768);
        __syncthreads();
    }

    const int er = lane >> 2, ec = (lane & 3) * 2;
    if (mode < 3) {
        __nv_bfloat16* dh = g_hd_h[mode];
        __nv_bfloat16* dl = g_hd_l[mode];
#pragma unroll
        for (int mi = 0; mi < 4; mi++)
#pragma unroll
            for (int nj = 0; nj < 4; nj++) {
                const int col = bn + wx * 32 + nj * 8 + ec;
                const float b0 = __ldg(bias + col), b1 = __ldg(bias + col + 1);
                const int row0 = bm + wy * 64 + mi * 16 + er;
#pragma unroll
                for (int h = 0; h < 2; h++) {
                    const int row = row0 + h * 8;
                    uint32_t hv, lv;
                    split2(acc[mi][nj][h * 2] + b0, acc[mi][nj][h * 2 + 1] + b1, hv, lv);
                    int bb = row >> 11, ss = row & (S_ - 1), hh = col >> 6, dd = col & (DH_ - 1);
                    size_t idx = (((size_t)(bb * H_ + hh)) * S_ + ss) * DH_ + dd;
                    *(uint32_t*)(dh + idx) = hv;
                    *(uint32_t*)(dl + idx) = lv;
                }
            }
    } else {
#pragma unroll
        for (int mi = 0; mi < 4; mi++)
#pragma unroll
            for (int nj = 0; nj < 4; nj++) {
                const int col = bn + wx * 32 + nj * 8 + ec;
                const float b0 = __ldg(bias + col), b1 = __ldg(bias + col + 1);
                const int row0 = bm + wy * 64 + mi * 16 + er;
#pragma unroll
                for (int h = 0; h < 2; h++) {
                    float2 v = make_float2(acc[mi][nj][h * 2] + b0, acc[mi][nj][h * 2 + 1] + b1);
                    *(float2*)(Yout + (size_t)(row0 + h * 8) * D_ + col) = v;
                }
            }
    }
}

// ---------------- fused attention: logits + softmax + p@V --------------------
// One CTA per (bh, 128-q-tile).  SMEM (96KB):
//  pass1: Q @0 (hi 16K, lo 16K); K buf0 @32K, K buf1 @64K (hi 16K, lo 16K each)
//  pass2: P buf0 @0, P buf1 @32K (hi 16K, lo 16K); V buf0 @64K (hi 8K, lo 8K), V buf1 @80K
__global__ void __launch_bounds__(256, 2) fused_attn(float* __restrict__ attn)
{
    extern __shared__ __align__(1024) char smp[];
    __shared__ float2 s_red[128][4];      // (max, sumexp) partials per wx
    __shared__ float sm_m[128], sm_s[128], sm_i[128];
    uint32_t sb = smem_u32(smp);
    const int t = threadIdx.x, lane = t & 31, wid = t >> 5;
    const int bh = blockIdx.y, q0 = blockIdx.x * 128;
    const __nv_bfloat16* Qh = g_hd_h[0] + (size_t)bh * S_ * DH_;
    const __nv_bfloat16* Ql = g_hd_l[0] + (size_t)bh * S_ * DH_;
    const __nv_bfloat16* Kh = g_hd_h[1] + (size_t)bh * S_ * DH_;
    const __nv_bfloat16* Kl = g_hd_l[1] + (size_t)bh * S_ * DH_;
    const __nv_bfloat16* Vh = g_hd_h[2] + (size_t)bh * S_ * DH_;
    const __nv_bfloat16* Vl = g_hd_l[2] + (size_t)bh * S_ * DH_;
    float* A = attn + (size_t)bh * S_ * S_;

    if (t < 128) { sm_m[t] = -1e30f; sm_s[t] = 0.0f; }

    // ---- load Q (group with K0) ----
#pragma unroll
    for (int i = 0; i < 4; i++) {
        int e = i * 256 + t, r = e >> 3, c8 = e & 7;
        uint32_t so = r * 128 + ((c8 ^ (r & 7)) << 4);
        cp16(sb + so,         Qh + (size_t)(q0 + r) * DH_ + c8 * 8);
        cp16(sb + 16384 + so, Ql + (size_t)(q0 + r) * DH_ + c8 * 8);
    }
#define FA_KPF(kt) do { \
    uint32_t kb_ = sb + 32768 + ((kt) & 1) * 32768; \
    _Pragma("unroll") \
    for (int i_ = 0; i_ < 4; i_++) { \
        int e_ = i_ * 256 + t, r_ = e_ >> 3, c8_ = e_ & 7; \
        uint32_t so_ = r_ * 128 + ((c8_ ^ (r_ & 7)) << 4); \
        cp16(kb_ + so_,         Kh + (size_t)((kt) * 128 + r_) * DH_ + c8_ * 8); \
        cp16(kb_ + 16384 + so_, Kl + (size_t)((kt) * 128 + r_) * DH_ + c8_ * 8); \
    } \
    CP_COMMIT(); \
} while (0)

    FA_KPF(0);          // group0 = Q + K0
    FA_KPF(1);          // group1 = K1

    // ================= PASS 1: S = 0.125 * Q K^T, online stats =================
    {
        const int wy = wid >> 2, wx = wid & 3;       // 2 x 4 warps, warp 64q x 32k
        const int er = lane >> 2, ec = (lane & 3) * 2;
#pragma unroll 1
        for (int kt = 0; kt < 16; kt++) {
            if (kt == 15) cp_wait<0>(); else cp_wait<1>();
            __syncthreads();                          // also protects s_red reuse

            float acc[4][4][4];
#pragma unroll
            for (int i = 0; i < 4; i++)
#pragma unroll
                for (int j = 0; j < 4; j++)
#pragma unroll
                    for (int k = 0; k < 4; k++) acc[i][j][k] = 0.0f;

            const uint32_t aQH = sb, aQL = sb + 16384;
            const uint32_t aKH = sb + 32768 + (kt & 1) * 32768, aKL = aKH + 16384;
#pragma unroll
            for (int s = 0; s < 4; s++) {
                const int rA0 = wy * 64 + ((lane >> 3) & 1) * 8 + (lane & 7);
                const int cA = 2 * s + (lane >> 4);
                uint32_t ah[4][4], al[4][4];
#pragma unroll
                for (int mi = 0; mi < 4; mi++) {
                    int r = rA0 + mi * 16;
                    uint32_t off = r * 128 + ((cA ^ (r & 7)) << 4);
                    ldsm4(ah[mi], aQH + off);
                    ldsm4(al[mi], aQL + off);
                }
                uint32_t bhf[2][4], blf[2][4];
                const int cB = 2 * s + ((lane >> 3) & 1);
#pragma unroll
                for (int nh = 0; nh < 2; nh++) {
                    int r = wx * 32 + nh * 16 + ((lane >> 4) & 1) * 8 + (lane & 7);
                    uint32_t off = r * 128 + ((cB ^ (r & 7)) << 4);
                    ldsm4(bhf[nh], aKH + off);
                    ldsm4(blf[nh], aKL + off);
                }
#pragma unroll
                for (int mi = 0; mi < 4; mi++)
#pragma unroll
                    for (int nj = 0; nj < 4; nj++) {
                        uint32_t b0 = bhf[nj >> 1][(nj & 1) * 2], b1 = bhf[nj >> 1][(nj & 1) * 2 + 1];
                        uint32_t c0 = blf[nj >> 1][(nj & 1) * 2], c1 = blf[nj >> 1][(nj & 1) * 2 + 1];
                        mma_bf16(acc[mi][nj], ah[mi], b0, b1);
                        mma_bf16(acc[mi][nj], ah[mi], c0, c1);
                        mma_bf16(acc[mi][nj], al[mi], b0, b1);
                    }
            }
#pragma unroll
            for (int i = 0; i < 4; i++)
#pragma unroll
                for (int j = 0; j < 4; j++)
#pragma unroll
                    for (int k = 0; k < 4; k++) acc[i][j][k] *= 0.125f;

            // warp-local (max, sumexp) partials — one pass, one sync
#pragma unroll
            for (int mi = 0; mi < 4; mi++)
#pragma unroll
                for (int h = 0; h < 2; h++) {
                    float m = -1e30f;
#pragma unroll
                    for (int nj = 0; nj < 4; nj++)
                        m = fmaxf(m, fmaxf(acc[mi][nj][h * 2], acc[mi][nj][h * 2 + 1]));
                    m = fmaxf(m, __shfl_xor_sync(0xffffffffu, m, 1));
                    m = fmaxf(m, __shfl_xor_sync(0xffffffffu, m, 2));
                    float s = 0.0f;
#pragma unroll
                    for (int nj = 0; nj < 4; nj++)
                        s += __expf(acc[mi][nj][h * 2] - m) + __expf(acc[mi][nj][h * 2 + 1] - m);
                    s += __shfl_xor_sync(0xffffffffu, s, 1);
                    s += __shfl_xor_sync(0xffffffffu, s, 2);
                    if ((lane & 3) == 0)
                        s_red[wy * 64 + mi * 16 + h * 8 + er][wx] = make_float2(m, s);
                }
            __syncthreads();
            if (t < 128) {
                float2 p0 = s_red[t][0], p1 = s_red[t][1], p2 = s_red[t][2], p3 = s_red[t][3];
                float mt = fmaxf(fmaxf(p0.x, p1.x), fmaxf(p2.x, p3.x));
                float st = p0.y * __expf(p0.x - mt) + p1.y * __expf(p1.x - mt)
                         + p2.y * __expf(p2.x - mt) + p3.y * __expf(p3.x - mt);
                float mo = sm_m[t];
                float mn = fmaxf(mo, mt);
                sm_s[t] = sm_s[t] * __expf(mo - mn) + st * __expf(mt - mn);
                sm_m[t] = mn;
            }
            // write raw S tile
            const int k0 = kt * 128;
#pragma unroll
            for (int mi = 0; mi < 4; mi++)
#pragma unroll
                for (int nj = 0; nj < 4; nj++) {
                    const int col = k0 + wx * 32 + nj * 8 + ec;
                    const int row0 = q0 + wy * 64 + mi * 16 + er;
#pragma unroll
                    for (int h = 0; h < 2; h++) {
                        float2 v = make_float2(acc[mi][nj][h * 2], acc[mi][nj][h * 2 + 1]);
                        *(float2*)(A + (size_t)(row0 + h * 8) * S_ + col) = v;
                    }
                }
            if (kt + 2 < 16) FA_KPF(kt + 2);
        }
    }
    __syncthreads();
    if (t < 128) sm_i[t] = 1.0f / sm_s[t];
    __syncthreads();

    // ================= PASS 2: p = exp(S-m)*inv ; O = p @ V ====================
    {
        const int wy = wid >> 1, wx = wid & 1;       // 4 x 2 warps, warp 32q x 32d
        float acc[2][4][4];
#pragma unroll
        for (int i = 0; i < 2; i++)
#pragma unroll
            for (int j = 0; j < 4; j++)
#pragma unroll
                for (int k = 0; k < 4; k++) acc[i][j][k] = 0.0f;

        float4 ra[8];
        const int arow = t >> 4, ac4 = t & 15;

#define FA_VPF(c) do { \
    const int kc_ = (c) * 64; \
    uint32_t vb_ = sb + 65536 + ((c) & 1) * 16384; \
    _Pragma("unroll") \
    for (int i_ = 0; i_ < 2; i_++) { \
        int e_ = i_ * 256 + t, r_ = e_ >> 3, c8_ = e_ & 7; \
        uint32_t so_ = r_ * 128 + ((c8_ ^ (r_ & 7)) << 4); \
        cp16(vb_ + so_,        Vh + (size_t)(kc_ + r_) * DH_ + c8_ * 8); \
        cp16(vb_ + 8192 + so_, Vl + (size_t)(kc_ + r_) * DH_ + c8_ * 8); \
    } \
    CP_COMMIT(); \
} while (0)

#define FA_LDA(c) do { \
    const int kc_ = (c) * 64; \
    _Pragma("unroll") \
    for (int i_ = 0; i_ < 8; i_++) \
        ra[i_] = *(const float4*)(A + (size_t)(q0 + i_ * 16 + arow) * S_ + kc_ + ac4 * 4); \
} while (0)

#define FA_STA(c) do { \
    const int kc_ = (c) * 64; \
    char* ab_ = smp + ((c) & 1) * 32768; \
    _Pragma("unroll") \
    for (int i_ = 0; i_ < 8; i_++) { \
        int r_ = i_ * 16 + arow; \
        const float m_ = sm_m[r_], in_ = sm_i[r_]; \
        float4 p_; \
        p_.x = __expf(ra[i_].x - m_) * in_; \
        p_.y = __expf(ra[i_].y - m_) * in_; \
        p_.z = __expf(ra[i_].z - m_) * in_; \
        p_.w = __expf(ra[i_].w - m_) * in_; \
        *(float4*)(A + (size_t)(q0 + r_) * S_ + kc_ + ac4 * 4) = p_; \
        uint32_t h01, l01, h23, l23; \
        split2(p_.x, p_.y, h01, l01); \
        split2(p_.z, p_.w, h23, l23); \
        uint32_t so_ = r_ * 128 + ((((ac4 >> 1) ^ (r_ & 7)) << 4)) + (ac4 & 1) * 8; \
        *(uint2*)(ab_ + so_)         = make_uint2(h01, h23); \
        *(uint2*)(ab_ + 16384 + so_) = make_uint2(l01, l23); \
    } \
} while (0)

#define FA_MMA(c) do { \
    uint32_t aAH = sb + ((c) & 1) * 32768, aAL = aAH + 16384; \
    uint32_t aBH = sb + 65536 + ((c) & 1) * 16384, aBL = aBH + 8192; \
    _Pragma("unroll") \
    for (int s = 0; s < 4; s++) { \
        const int rA0 = wy * 32 + ((lane >> 3) & 1) * 8 + (lane & 7); \
        const int cA = 2 * s + (lane >> 4); \
        uint32_t ah[2][4], al[2][4]; \
        _Pragma("unroll") \
        for (int mi = 0; mi < 2; mi++) { \
            int r = rA0 + mi * 16; \
            uint32_t off = r * 128 + ((cA ^ (r & 7)) << 4); \
            ldsm4(ah[mi], aAH + off); \
            ldsm4(al[mi], aAL + off); \
        } \
        const int rB = 16 * s + ((lane >> 3) & 1) * 8 + (lane & 7); \
        uint32_t bh2[2][4], bl2[2][4]; \
        _Pragma("unroll") \
        for (int nh = 0; nh < 2; nh++) { \
            int cB = ((wx * 32 + nh * 16) >> 3) + ((lane >> 4) & 1); \
            uint32_t off = rB * 128 + ((cB ^ (rB & 7)) << 4); \
            ldsm4t(bh2[nh], aBH + off); \
            ldsm4t(bl2[nh], aBL + off); \
        } \
        _Pragma("unroll") \
        for (int mi = 0; mi < 2; mi++) \
            _Pragma("unroll") \
            for (int nj = 0; nj < 4; nj++) { \
                uint32_t b0 = bh2[nj >> 1][(nj & 1) * 2], b1 = bh2[nj >> 1][(nj & 1) * 2 + 1]; \
                uint32_t c0 = bl2[nj >> 1][(nj & 1) * 2], c1 = bl2[nj >> 1][(nj & 1) * 2 + 1]; \
                mma_bf16(acc[mi][nj], ah[mi], b0, b1); \
                mma_bf16(acc[mi][nj], ah[mi], c0, c1); \
                mma_bf16(acc[mi][nj], al[mi], b0, b1); \
            } \
    } \
} while (0)

        // reverse order: most recently written S tiles are read first (L2 warm)
        FA_VPF(31);
        FA_LDA(31);
        FA_STA(31);
#pragma unroll 1
        for (int c = 31; c >= 0; c--) {
            if (c > 0) { FA_VPF(c - 1); FA_LDA(c - 1); }
            if (c > 0) cp_wait<1>(); else cp_wait<0>();
            __syncthreads();
            FA_MMA(c);
            if (c > 0) FA_STA(c - 1);
            __syncthreads();
        }

        const int bb = bh >> 4, hh = bh & (H_ - 1);
        const int er = lane >> 2, ec = (lane & 3) * 2;
#pragma unroll
        for (int mi = 0; mi < 2; mi++)
#pragma unroll
            for (int nj = 0; nj < 4; nj++) {
                const int dd = wx * 32 + nj * 8 + ec;
                const int row0 = q0 + wy * 32 + mi * 16 + er;
#pragma unroll
                for (int h = 0; h < 2; h++) {
                    const int ss = row0 + h * 8;
                    uint32_t hv, lv;
                    split2(acc[mi][nj][h * 2], acc[mi][nj][h * 2 + 1], hv, lv);
                    size_t idx = ((size_t)(bb * S_ + ss)) * D_ + hh * DH_ + dd;
                    *(uint32_t*)(g_cat_h + idx) = hv;
                    *(uint32_t*)(g_cat_l + idx) = lv;
                }
            }
    }
}

// ---------------- launch ------------------------------------------------------
extern "C" void kernel_launch(void* const* d_in, const int* in_sizes, int n_in,
                              void* d_out, int out_size)
{
    const float* q  = (const float*)d_in[0];
    const float* k  = (const float*)d_in[1];
    const float* v  = (const float*)d_in[2];
    const float* Wq = (const float*)d_in[3];
    const float* bq = (const float*)d_in[4];
    const float* Wk = (const float*)d_in[5];
    const float* bk = (const float*)d_in[6];
    const float* Wv = (const float*)d_in[7];
    const float* bv = (const float*)d_in[8];
    const float* Wc = (const float*)d_in[9];
    const float* bc = (const float*)d_in[10];

    float* out  = (float*)d_out;
    float* attn = out + OUT_ELEMS;

    const int SM_PROJ = 98304;
    const int SM_FA   = 98304;
    cudaFuncSetAttribute(proj_tc,    cudaFuncAttributeMaxDynamicSharedMemorySize, SM_PROJ);
    cudaFuncSetAttribute(fused_attn, cudaFuncAttributeMaxDynamicSharedMemorySize, SM_FA);

    split_all<<<16384, 256>>>(q, k, v, Wq, Wk, Wv, Wc);

    proj_tc<<<dim3(8, 32, 3), 256, SM_PROJ>>>(bq, bk, bv, bc, nullptr, 0);

    fused_attn<<<dim3(16, 32), 256, SM_FA>>>(attn);

    proj_tc<<<dim3(8, 32, 1), 256, SM_PROJ>>>(bq, bk, bv, bc, out, 3);
}